// round 10
// baseline (speedup 1.0000x reference)
#include <cuda_runtime.h>
#include <cuda_fp16.h>
#include <math.h>
#include <stdint.h>

// ---------------- problem constants ----------------
#define BB      4
#define LL      4096
#define DMODEL  1024
#define DINNER  2048
#define NH      32
#define HD      64
#define DIP     4256
#define NROWS   (BB*LL)
#define CHUNKT  64
#define NT      (LL/CHUNKT)
#define DTCOL   (DINNER + 2176)   // 4224

// ---------------- GEMM tiling ----------------
#define BM 128
#define BN 128
#define BK 64                     // fp16 K elems per stage (128 bytes per row)
#define STAGES 4
#define TILE_B  16384             // 128 rows x 128 bytes
#define STAGE_B (3*TILE_B)        // Ah, Bh, Bl
#define SMEM_DYN (STAGES*STAGE_B + 1024)

// ---------------- scratch ----------------
__device__ float g_zxcdt[(size_t)NROWS * DIP];
__device__ float g_e[NROWS * NH];
__device__ float g_w[NROWS * NH];
__device__ float g_carry[BB * NT * NH * HD];
__device__ float g_Etot[BB * NT * NH];
__device__ float g_S[BB * NT * NH * HD];
__device__ float g_scal[2];
__device__ __half g_uh[(size_t)NROWS * DMODEL];
__device__ __half g_w1h[(size_t)DIP * DMODEL];
__device__ __half g_w1l[(size_t)DIP * DMODEL];
__device__ __half g_yh[(size_t)NROWS * DINNER];
__device__ __half g_w2h[(size_t)DMODEL * DINNER];
__device__ __half g_w2l[(size_t)DMODEL * DINNER];

// ---------------- helpers ----------------
__device__ __forceinline__ uint32_t s2u(const void* p) {
    uint32_t a;
    asm("{ .reg .u64 t; cvta.to.shared.u64 t, %1; cvt.u32.u64 %0, t; }" : "=r"(a) : "l"(p));
    return a;
}
#define SWZ(x) ((x) ^ (((x) >> 3) & 0x70))

__device__ __forceinline__ void cp16(uint32_t dst, const void* src) {
    asm volatile("cp.async.cg.shared.global [%0], [%1], 16;"
                 :: "r"(dst), "l"(src) : "memory");
}
__device__ __forceinline__ void ldm4(uint32_t* r, uint32_t addr) {
    asm volatile("ldmatrix.sync.aligned.m8n8.x4.shared.b16 {%0,%1,%2,%3}, [%4];"
                 : "=r"(r[0]), "=r"(r[1]), "=r"(r[2]), "=r"(r[3]) : "r"(addr));
}
__device__ __forceinline__ void mma16816(float* d, const uint32_t* a, const uint32_t* b) {
    asm volatile(
        "mma.sync.aligned.m16n8k16.row.col.f32.f16.f16.f32 "
        "{%0,%1,%2,%3}, {%4,%5,%6,%7}, {%8,%9}, {%0,%1,%2,%3};"
        : "+f"(d[0]), "+f"(d[1]), "+f"(d[2]), "+f"(d[3])
        : "r"(a[0]), "r"(a[1]), "r"(a[2]), "r"(a[3]), "r"(b[0]), "r"(b[1]));
}

// ============ HMMA GEMM: C[M,N] = Ah*(Bh+Bl)^T (+bias) ============
// Ah: [M,K] fp16 K-major; Bh,Bl: [N,K] fp16 K-major; C: [M,N] fp32.
// 256 thr, warp grid 4(m) x 2(n), warp tile 32x64, BK=64, 4-stage cp.async.
// remap: if set and blockIdx.x==32, tile covers cols 4224.. (skips dead 4096..4223)
__global__ void __launch_bounds__(256, 1) k_mm(
    const __half* __restrict__ Ah,
    const __half* __restrict__ Bh, const __half* __restrict__ Bl,
    const float* __restrict__ bias, float* __restrict__ C,
    int M, int N, int K, int remap)
{
    extern __shared__ char smraw[];
    const uint32_t sb = (s2u(smraw) + 1023u) & ~1023u;
    const int t = threadIdx.x;
    const int wid = t >> 5, lane = t & 31;
    const int wm = wid & 3, wn = wid >> 2;       // warp tile origin (wm*32, wn*64)
    const int m0 = blockIdx.y * BM;
    int n0 = blockIdx.x * BN;
    if (remap && (int)blockIdx.x == 32) n0 = 4224;
    const int nk = K / BK;

    auto load_tile = [&](int kt, int st) {
        const uint32_t base = sb + st * STAGE_B;
        const size_t kof = (size_t)kt * BK;
#pragma unroll
        for (int i = 0; i < 4; i++) {
            int id = t + i * 256;
            int r = id >> 3, c = id & 7;
            uint32_t off = SWZ((uint32_t)(r * 128 + c * 16));
            size_t ga = (size_t)(m0 + r) * K + kof + c * 8;
            cp16(base + off, Ah + ga);
            int gn = n0 + r; if (gn >= N) gn = N - 1;   // clamp (junk cols unstored)
            size_t gb = (size_t)gn * K + kof + c * 8;
            cp16(base + TILE_B + off, Bh + gb);
            cp16(base + 2 * TILE_B + off, Bl + gb);
        }
        asm volatile("cp.async.commit_group;" ::: "memory");
    };

    float acc[2][8][4];
#pragma unroll
    for (int i = 0; i < 2; i++)
#pragma unroll
        for (int j = 0; j < 8; j++)
#pragma unroll
            for (int v = 0; v < 4; v++) acc[i][j][v] = 0.f;

    load_tile(0, 0);
    load_tile(1, 1);
    load_tile(2, 2);

    for (int kt = 0; kt < nk; kt++) {
        asm volatile("cp.async.wait_group 2;" ::: "memory");
        __syncthreads();

        // issue next-next-next tile load before compute (stage (kt+3)%4 is free)
        if (kt + 3 < nk) {
            load_tile(kt + 3, (kt + 3) % STAGES);
        } else {
            asm volatile("cp.async.commit_group;" ::: "memory");   // keep group count invariant
        }

        const int st = kt % STAGES;
        const uint32_t abase = sb + st * STAGE_B;
        const uint32_t bhb = abase + TILE_B;
        const uint32_t blb = abase + 2 * TILE_B;

#pragma unroll
        for (int k16 = 0; k16 < 4; k16++) {
            const int kbyte = k16 * 32;
            uint32_t ah[2][4], bhf[16], blf[16];
#pragma unroll
            for (int mt = 0; mt < 2; mt++) {
                int r = wm * 32 + mt * 16 + (lane & 15);
                int cb = kbyte + ((lane >> 4) << 4);
                uint32_t off = SWZ((uint32_t)(r * 128 + cb));
                ldm4(ah[mt], abase + off);
            }
#pragma unroll
            for (int bt = 0; bt < 4; bt++) {
                int r = wn * 64 + bt * 16 + (lane & 7) + ((lane & 16) >> 1);
                int cb = kbyte + ((lane & 8) << 1);
                uint32_t off = SWZ((uint32_t)(r * 128 + cb));
                ldm4(&bhf[bt * 4], bhb + off);
                ldm4(&blf[bt * 4], blb + off);
            }
#pragma unroll
            for (int mt = 0; mt < 2; mt++)
#pragma unroll
                for (int nt = 0; nt < 8; nt++) {
                    mma16816(acc[mt][nt], ah[mt], &bhf[nt * 2]);
                    mma16816(acc[mt][nt], ah[mt], &blf[nt * 2]);
                }
        }
        __syncthreads();
    }

    // ---- epilogue: direct float2 stores ----
    const int qr = lane >> 2;
    const int qc = (lane & 3) * 2;
#pragma unroll
    for (int mt = 0; mt < 2; mt++) {
        const int gmA = m0 + wm * 32 + mt * 16 + qr;
#pragma unroll
        for (int nt = 0; nt < 8; nt++) {
            const int gn = n0 + wn * 64 + nt * 8 + qc;
            if (gn < N) {
                float bx = 0.f, by = 0.f;
                if (bias) { bx = bias[gn]; by = bias[gn + 1]; }
                float2 v0 = make_float2(acc[mt][nt][0] + bx, acc[mt][nt][1] + by);
                float2 v1 = make_float2(acc[mt][nt][2] + bx, acc[mt][nt][3] + by);
                *(float2*)(C + (size_t)gmA * N + gn) = v0;
                *(float2*)(C + (size_t)(gmA + 8) * N + gn) = v1;
            }
        }
    }
}

// ---------------- fp32 -> fp16 (plain) ----------------
__global__ void k_split_h(const float* __restrict__ s, __half* __restrict__ h, size_t n)
{
    size_t i = (size_t)blockIdx.x * blockDim.x + threadIdx.x;
    if (i >= n) return;
    h[i] = __float2half_rn(s[i]);
}

// ---------------- fp32 -> (hi, lo) fp16 ----------------
__global__ void k_split_hl(const float* __restrict__ s, __half* __restrict__ h,
                           __half* __restrict__ l, size_t n)
{
    size_t i = (size_t)blockIdx.x * blockDim.x + threadIdx.x;
    if (i >= n) return;
    float x = s[i];
    __half hh = __float2half_rn(x);
    h[i] = hh;
    l[i] = __float2half_rn(x - __half2float(hh));
}

// ---------------- tiny reductions ----------------
__global__ void k_reduce_bwbb(const float* __restrict__ bw, const float* __restrict__ bb) {
    __shared__ float s1[128], s2[128];
    int t = threadIdx.x;
    s1[t] = bw[t]; s2[t] = bb[t];
    __syncthreads();
    for (int o = 64; o > 0; o >>= 1) {
        if (t < o) { s1[t] += s1[t + o]; s2[t] += s2[t + o]; }
        __syncthreads();
    }
    if (t == 0) { g_scal[0] = s1[0]; g_scal[1] = s2[0]; }
}

// ---------------- e/w precompute ----------------
__global__ void k_ew(const float* __restrict__ reward,
                     const float* __restrict__ dt_bias,
                     const float* __restrict__ A_log)
{
    int idx = blockIdx.x * blockDim.x + threadIdx.x;
    if (idx >= NROWS * NH) return;
    int row = idx / NH;
    int h = idx % NH;
    float raw = g_zxcdt[(size_t)row * DIP + DTCOL + h] + dt_bias[h];
    float dt = (raw > 20.f) ? raw : log1pf(expf(raw));
    float a = -expf(A_log[h]);
    float Bs = reward[row] * g_scal[0] + g_scal[1];
    g_e[idx] = expf(a * dt);
    g_w[idx] = Bs * dt;
}

// ---------------- pass A: fused conv + local scan, carries only ----------------
// one block per (b, chunk tt, h); 64 threads = p
__global__ void __launch_bounds__(64) k_scanA(const float* __restrict__ conv_w,
                                              const float* __restrict__ conv_b)
{
    const int bid = blockIdx.x;
    const int h = bid % NH;
    const int tt = (bid / NH) % NT;
    const int b = bid / (NH * NT);
    const int p = threadIdx.x;
    const int row0 = b * LL + tt * CHUNKT;
    const int c = h * HD + p;                 // x channel
    const size_t col = DINNER + c;            // zxcdt column

    __shared__ float se[CHUNKT], sw[CHUNKT];
    se[p] = g_e[(row0 + p) * NH + h];
    sw[p] = g_w[(row0 + p) * NH + h];
    __syncthreads();

    const float w0 = conv_w[c * 4 + 0], w1 = conv_w[c * 4 + 1];
    const float w2 = conv_w[c * 4 + 2], w3 = conv_w[c * 4 + 3];
    const float cb = conv_b[c];

    float x0 = 0.f, x1 = 0.f, x2 = 0.f;
    if (tt > 0) {
        x0 = g_zxcdt[(size_t)(row0 - 3) * DIP + col];
        x1 = g_zxcdt[(size_t)(row0 - 2) * DIP + col];
        x2 = g_zxcdt[(size_t)(row0 - 1) * DIP + col];
    }
    float r = 0.f, Ep = 1.f;
    for (int i = 0; i < CHUNKT; i++) {
        float xn = g_zxcdt[(size_t)(row0 + i) * DIP + col];
        float a = cb + x0 * w0 + x1 * w1 + x2 * w2 + xn * w3;
        float xs = 1.f / (1.f + expf(-a)) + 0.1f * a;
        r = se[i] * r + sw[i] * xs;
        x0 = x1; x1 = x2; x2 = xn;
        Ep *= se[i];
    }
    g_carry[bid * HD + p] = r;
    if (p == 0) {
        float E = 1.f;
        for (int i = 0; i < CHUNKT; i++) E *= se[i];
        g_Etot[bid] = E;
    }
    (void)Ep;
}

// ---------------- pass B: scan carries across chunks ----------------
__global__ void k_scanB()
{
    int idx = blockIdx.x * blockDim.x + threadIdx.x;
    if (idx >= BB * NH * HD) return;
    int p = idx % HD;
    int h = (idx / HD) % NH;
    int b = idx / (HD * NH);
    float c = 0.f;
    for (int tt = 0; tt < NT; tt++) {
        int bid = (b * NT + tt) * NH + h;
        g_S[bid * HD + p] = c;
        c = g_Etot[bid] * c + g_carry[bid * HD + p];
    }
}

// ---------------- pass C: conv + scan + inter-chunk fixup + gate -> fp16 yh ----------------
__global__ void __launch_bounds__(64) k_scanC(const float* __restrict__ conv_w,
                                              const float* __restrict__ conv_b)
{
    const int bid = blockIdx.x;
    const int h = bid % NH;
    const int tt = (bid / NH) % NT;
    const int b = bid / (NH * NT);
    const int p = threadIdx.x;
    const int row0 = b * LL + tt * CHUNKT;
    const int c = h * HD + p;
    const size_t col = DINNER + c;

    __shared__ float se[CHUNKT], sw[CHUNKT], sp[CHUNKT];
    se[p] = g_e[(row0 + p) * NH + h];
    sw[p] = g_w[(row0 + p) * NH + h];
    __syncthreads();
    if (p == 0) {
        float r = 1.f;
        for (int i = 0; i < CHUNKT; i++) { r *= se[i]; sp[i] = r; }
    }
    __syncthreads();

    const float w0 = conv_w[c * 4 + 0], w1 = conv_w[c * 4 + 1];
    const float w2 = conv_w[c * 4 + 2], w3 = conv_w[c * 4 + 3];
    const float cb = conv_b[c];
    const float Sv = g_S[bid * HD + p];

    float x0 = 0.f, x1 = 0.f, x2 = 0.f;
    if (tt > 0) {
        x0 = g_zxcdt[(size_t)(row0 - 3) * DIP + col];
        x1 = g_zxcdt[(size_t)(row0 - 2) * DIP + col];
        x2 = g_zxcdt[(size_t)(row0 - 1) * DIP + col];
    }
    float r = 0.f;
    for (int i = 0; i < CHUNKT; i++) {
        const size_t rowi = (size_t)(row0 + i);
        float xn = g_zxcdt[rowi * DIP + col];
        float a = cb + x0 * w0 + x1 * w1 + x2 * w2 + xn * w3;
        float xs = 1.f / (1.f + expf(-a)) + 0.1f * a;
        r = se[i] * r + sw[i] * xs;
        x0 = x1; x1 = x2; x2 = xn;
        float y = r + Sv * sp[i];
        float z = g_zxcdt[rowi * DIP + c];
        float g = y * (1.f / (1.f + expf(-z)) + 0.1f * z);
        g_yh[rowi * DINNER + c] = __float2half_rn(g);
    }
}

// ---------------- launch ----------------
extern "C" void kernel_launch(void* const* d_in, const int* in_sizes, int n_in,
                              void* d_out, int out_size)
{
    const float* u       = (const float*)d_in[0];
    const float* reward  = (const float*)d_in[1];
    const float* in_w    = (const float*)d_in[2];
    const float* in_b    = (const float*)d_in[3];
    const float* conv_w  = (const float*)d_in[4];
    const float* conv_b  = (const float*)d_in[5];
    const float* bw      = (const float*)d_in[6];
    const float* bb      = (const float*)d_in[7];
    const float* dt_bias = (const float*)d_in[8];
    const float* A_log   = (const float*)d_in[9];
    const float* out_w   = (const float*)d_in[10];
    float* out = (float*)d_out;

    cudaFuncSetAttribute(k_mm, cudaFuncAttributeMaxDynamicSharedMemorySize, SMEM_DYN);

    float* zxcdt;
    __half *uh, *w1h, *w1l, *yh, *w2h, *w2l;
    cudaGetSymbolAddress((void**)&zxcdt, g_zxcdt);
    cudaGetSymbolAddress((void**)&uh, g_uh);
    cudaGetSymbolAddress((void**)&w1h, g_w1h);
    cudaGetSymbolAddress((void**)&w1l, g_w1l);
    cudaGetSymbolAddress((void**)&yh, g_yh);
    cudaGetSymbolAddress((void**)&w2h, g_w2h);
    cudaGetSymbolAddress((void**)&w2l, g_w2l);

    // conversions
    {
        size_t n = (size_t)NROWS * DMODEL;
        k_split_h<<<(unsigned)((n + 255) / 256), 256>>>(u, uh, n);
    }
    {
        size_t n = (size_t)DIP * DMODEL;
        k_split_hl<<<(unsigned)((n + 255) / 256), 256>>>(in_w, w1h, w1l, n);
    }
    {
        size_t n = (size_t)DMODEL * DINNER;
        k_split_hl<<<(unsigned)((n + 255) / 256), 256>>>(out_w, w2h, w2l, n);
    }

    // GEMM1: zxcdt[16384, {0..4095, 4224..4255}] = u @ in_w^T + in_b  (K=1024)
    // grid.x = 33: tiles 0..31 = cols 0..4095, tile 32 remapped to cols 4224..4255
    {
        dim3 grid(33, NROWS / BM);
        k_mm<<<grid, 256, SMEM_DYN>>>(uh, w1h, w1l, in_b, zxcdt, NROWS, DIP, DMODEL, 1);
    }

    k_reduce_bwbb<<<1, 128>>>(bw, bb);
    {
        int n = NROWS * NH;
        k_ew<<<(n + 255) / 256, 256>>>(reward, dt_bias, A_log);
    }
    k_scanA<<<BB * NT * NH, 64>>>(conv_w, conv_b);
    {
        int n = BB * NH * HD;
        k_scanB<<<(n + 255) / 256, 256>>>();
    }
    k_scanC<<<BB * NT * NH, 64>>>(conv_w, conv_b);

    // GEMM2: out[16384, 1024] = y_gated @ out_w^T  (K=2048)
    {
        dim3 grid(DMODEL / BN, NROWS / BM);
        k_mm<<<grid, 256, SMEM_DYN>>>(yh, w2h, w2l, nullptr, out, NROWS, DMODEL, DINNER, 0);
    }
}

// round 11
// speedup vs baseline: 1.0003x; 1.0003x over previous
#include <cuda_runtime.h>
#include <cuda_fp16.h>
#include <math.h>
#include <stdint.h>

// ---------------- problem constants ----------------
#define BB      4
#define LL      4096
#define DMODEL  1024
#define DINNER  2048
#define NH      32
#define HD      64
#define DIP     4256
#define NROWS   (BB*LL)
#define CHUNKT  64
#define NT      (LL/CHUNKT)
#define DTCOL   (DINNER + 2176)   // 4224

// ---------------- GEMM tiling ----------------
#define BM 128
#define BN 128
#define BK 64                     // fp16 K elems per stage (128 bytes per row)
#define STAGES 4
#define TILE_B  16384             // 128 rows x 128 bytes
#define STAGE_B (3*TILE_B)        // Ah, Bh, Bl
#define SMEM_DYN (STAGES*STAGE_B + 1024)

// ---------------- scratch ----------------
__device__ float g_zxcdt[(size_t)NROWS * DIP];
__device__ float g_e[NROWS * NH];
__device__ float g_w[NROWS * NH];
__device__ float g_carry[BB * NT * NH * HD];
__device__ float g_Etot[BB * NT * NH];
__device__ float g_S[BB * NT * NH * HD];
__device__ float g_scal[2];
__device__ __half g_uh[(size_t)NROWS * DMODEL];
__device__ __half g_w1h[(size_t)DIP * DMODEL];
__device__ __half g_w1l[(size_t)DIP * DMODEL];
__device__ __half g_yh[(size_t)NROWS * DINNER];
__device__ __half g_w2h[(size_t)DMODEL * DINNER];
__device__ __half g_w2l[(size_t)DMODEL * DINNER];

// ---------------- helpers ----------------
__device__ __forceinline__ uint32_t s2u(const void* p) {
    uint32_t a;
    asm("{ .reg .u64 t; cvta.to.shared.u64 t, %1; cvt.u32.u64 %0, t; }" : "=r"(a) : "l"(p));
    return a;
}
#define SWZ(x) ((x) ^ (((x) >> 3) & 0x70))

__device__ __forceinline__ void cp16(uint32_t dst, const void* src) {
    asm volatile("cp.async.cg.shared.global [%0], [%1], 16;"
                 :: "r"(dst), "l"(src) : "memory");
}
__device__ __forceinline__ void ldm4(uint32_t* r, uint32_t addr) {
    asm volatile("ldmatrix.sync.aligned.m8n8.x4.shared.b16 {%0,%1,%2,%3}, [%4];"
                 : "=r"(r[0]), "=r"(r[1]), "=r"(r[2]), "=r"(r[3]) : "r"(addr));
}
__device__ __forceinline__ void mma16816(float* d, const uint32_t* a, const uint32_t* b) {
    asm volatile(
        "mma.sync.aligned.m16n8k16.row.col.f32.f16.f16.f32 "
        "{%0,%1,%2,%3}, {%4,%5,%6,%7}, {%8,%9}, {%0,%1,%2,%3};"
        : "+f"(d[0]), "+f"(d[1]), "+f"(d[2]), "+f"(d[3])
        : "r"(a[0]), "r"(a[1]), "r"(a[2]), "r"(a[3]), "r"(b[0]), "r"(b[1]));
}

// ============ HMMA GEMM: C[M,N] = Ah*(Bh+Bl)^T (+bias) ============
// Ah: [M,K] fp16 K-major; Bh,Bl: [N,K] fp16 K-major; C: [M,N] fp32.
// 256 thr, warp grid 4(m) x 2(n), warp tile 32x64, BK=64, 4-stage cp.async.
// remap: if set and blockIdx.x==32, tile covers cols 4224.. (skips dead 4096..4223)
__global__ void __launch_bounds__(256, 1) k_mm(
    const __half* __restrict__ Ah,
    const __half* __restrict__ Bh, const __half* __restrict__ Bl,
    const float* __restrict__ bias, float* __restrict__ C,
    int M, int N, int K, int remap)
{
    extern __shared__ char smraw[];
    const uint32_t sb = (s2u(smraw) + 1023u) & ~1023u;
    const int t = threadIdx.x;
    const int wid = t >> 5, lane = t & 31;
    const int wm = wid & 3, wn = wid >> 2;       // warp tile origin (wm*32, wn*64)
    const int m0 = blockIdx.y * BM;
    int n0 = blockIdx.x * BN;
    if (remap && (int)blockIdx.x == 32) n0 = 4224;
    const int nk = K / BK;

    auto load_tile = [&](int kt, int st) {
        const uint32_t base = sb + st * STAGE_B;
        const size_t kof = (size_t)kt * BK;
#pragma unroll
        for (int i = 0; i < 4; i++) {
            int id = t + i * 256;
            int r = id >> 3, c = id & 7;
            uint32_t off = SWZ((uint32_t)(r * 128 + c * 16));
            size_t ga = (size_t)(m0 + r) * K + kof + c * 8;
            cp16(base + off, Ah + ga);
            int gn = n0 + r; if (gn >= N) gn = N - 1;   // clamp (junk cols unstored)
            size_t gb = (size_t)gn * K + kof + c * 8;
            cp16(base + TILE_B + off, Bh + gb);
            cp16(base + 2 * TILE_B + off, Bl + gb);
        }
        asm volatile("cp.async.commit_group;" ::: "memory");
    };

    float acc[2][8][4];
#pragma unroll
    for (int i = 0; i < 2; i++)
#pragma unroll
        for (int j = 0; j < 8; j++)
#pragma unroll
            for (int v = 0; v < 4; v++) acc[i][j][v] = 0.f;

    load_tile(0, 0);
    load_tile(1, 1);
    load_tile(2, 2);

    for (int kt = 0; kt < nk; kt++) {
        asm volatile("cp.async.wait_group 2;" ::: "memory");
        __syncthreads();

        // issue next-next-next tile load before compute (stage (kt+3)%4 is free)
        if (kt + 3 < nk) {
            load_tile(kt + 3, (kt + 3) % STAGES);
        } else {
            asm volatile("cp.async.commit_group;" ::: "memory");   // keep group count invariant
        }

        const int st = kt % STAGES;
        const uint32_t abase = sb + st * STAGE_B;
        const uint32_t bhb = abase + TILE_B;
        const uint32_t blb = abase + 2 * TILE_B;

#pragma unroll
        for (int k16 = 0; k16 < 4; k16++) {
            const int kbyte = k16 * 32;
            uint32_t ah[2][4], bhf[16], blf[16];
#pragma unroll
            for (int mt = 0; mt < 2; mt++) {
                int r = wm * 32 + mt * 16 + (lane & 15);
                int cb = kbyte + ((lane >> 4) << 4);
                uint32_t off = SWZ((uint32_t)(r * 128 + cb));
                ldm4(ah[mt], abase + off);
            }
#pragma unroll
            for (int bt = 0; bt < 4; bt++) {
                int r = wn * 64 + bt * 16 + (lane & 7) + ((lane & 16) >> 1);
                int cb = kbyte + ((lane & 8) << 1);
                uint32_t off = SWZ((uint32_t)(r * 128 + cb));
                ldm4(&bhf[bt * 4], bhb + off);
                ldm4(&blf[bt * 4], blb + off);
            }
#pragma unroll
            for (int mt = 0; mt < 2; mt++)
#pragma unroll
                for (int nt = 0; nt < 8; nt++) {
                    mma16816(acc[mt][nt], ah[mt], &bhf[nt * 2]);
                    mma16816(acc[mt][nt], ah[mt], &blf[nt * 2]);
                }
        }
        __syncthreads();
    }

    // ---- epilogue: direct float2 stores ----
    const int qr = lane >> 2;
    const int qc = (lane & 3) * 2;
#pragma unroll
    for (int mt = 0; mt < 2; mt++) {
        const int gmA = m0 + wm * 32 + mt * 16 + qr;
#pragma unroll
        for (int nt = 0; nt < 8; nt++) {
            const int gn = n0 + wn * 64 + nt * 8 + qc;
            if (gn < N) {
                float bx = 0.f, by = 0.f;
                if (bias) { bx = bias[gn]; by = bias[gn + 1]; }
                float2 v0 = make_float2(acc[mt][nt][0] + bx, acc[mt][nt][1] + by);
                float2 v1 = make_float2(acc[mt][nt][2] + bx, acc[mt][nt][3] + by);
                *(float2*)(C + (size_t)gmA * N + gn) = v0;
                *(float2*)(C + (size_t)(gmA + 8) * N + gn) = v1;
            }
        }
    }
}

// ---------------- fp32 -> fp16 (plain) ----------------
__global__ void k_split_h(const float* __restrict__ s, __half* __restrict__ h, size_t n)
{
    size_t i = (size_t)blockIdx.x * blockDim.x + threadIdx.x;
    if (i >= n) return;
    h[i] = __float2half_rn(s[i]);
}

// ---------------- fp32 -> (hi, lo) fp16 ----------------
__global__ void k_split_hl(const float* __restrict__ s, __half* __restrict__ h,
                           __half* __restrict__ l, size_t n)
{
    size_t i = (size_t)blockIdx.x * blockDim.x + threadIdx.x;
    if (i >= n) return;
    float x = s[i];
    __half hh = __float2half_rn(x);
    h[i] = hh;
    l[i] = __float2half_rn(x - __half2float(hh));
}

// ---------------- tiny reductions ----------------
__global__ void k_reduce_bwbb(const float* __restrict__ bw, const float* __restrict__ bb) {
    __shared__ float s1[128], s2[128];
    int t = threadIdx.x;
    s1[t] = bw[t]; s2[t] = bb[t];
    __syncthreads();
    for (int o = 64; o > 0; o >>= 1) {
        if (t < o) { s1[t] += s1[t + o]; s2[t] += s2[t + o]; }
        __syncthreads();
    }
    if (t == 0) { g_scal[0] = s1[0]; g_scal[1] = s2[0]; }
}

// ---------------- e/w precompute ----------------
__global__ void k_ew(const float* __restrict__ reward,
                     const float* __restrict__ dt_bias,
                     const float* __restrict__ A_log)
{
    int idx = blockIdx.x * blockDim.x + threadIdx.x;
    if (idx >= NROWS * NH) return;
    int row = idx / NH;
    int h = idx % NH;
    float raw = g_zxcdt[(size_t)row * DIP + DTCOL + h] + dt_bias[h];
    float dt = (raw > 20.f) ? raw : log1pf(expf(raw));
    float a = -expf(A_log[h]);
    float Bs = reward[row] * g_scal[0] + g_scal[1];
    g_e[idx] = expf(a * dt);
    g_w[idx] = Bs * dt;
}

// ---------------- pass A: fused conv + local scan, carries only ----------------
// one block per (b, chunk tt, h); 64 threads = p
__global__ void __launch_bounds__(64) k_scanA(const float* __restrict__ conv_w,
                                              const float* __restrict__ conv_b)
{
    const int bid = blockIdx.x;
    const int h = bid % NH;
    const int tt = (bid / NH) % NT;
    const int b = bid / (NH * NT);
    const int p = threadIdx.x;
    const int row0 = b * LL + tt * CHUNKT;
    const int c = h * HD + p;                 // x channel
    const size_t col = DINNER + c;            // zxcdt column

    __shared__ float se[CHUNKT], sw[CHUNKT];
    se[p] = g_e[(row0 + p) * NH + h];
    sw[p] = g_w[(row0 + p) * NH + h];
    __syncthreads();

    const float w0 = conv_w[c * 4 + 0], w1 = conv_w[c * 4 + 1];
    const float w2 = conv_w[c * 4 + 2], w3 = conv_w[c * 4 + 3];
    const float cb = conv_b[c];

    float x0 = 0.f, x1 = 0.f, x2 = 0.f;
    if (tt > 0) {
        x0 = g_zxcdt[(size_t)(row0 - 3) * DIP + col];
        x1 = g_zxcdt[(size_t)(row0 - 2) * DIP + col];
        x2 = g_zxcdt[(size_t)(row0 - 1) * DIP + col];
    }
    float r = 0.f, Ep = 1.f;
    for (int i = 0; i < CHUNKT; i++) {
        float xn = g_zxcdt[(size_t)(row0 + i) * DIP + col];
        float a = cb + x0 * w0 + x1 * w1 + x2 * w2 + xn * w3;
        float xs = 1.f / (1.f + expf(-a)) + 0.1f * a;
        r = se[i] * r + sw[i] * xs;
        x0 = x1; x1 = x2; x2 = xn;
        Ep *= se[i];
    }
    g_carry[bid * HD + p] = r;
    if (p == 0) {
        float E = 1.f;
        for (int i = 0; i < CHUNKT; i++) E *= se[i];
        g_Etot[bid] = E;
    }
    (void)Ep;
}

// ---------------- pass B: scan carries across chunks ----------------
__global__ void k_scanB()
{
    int idx = blockIdx.x * blockDim.x + threadIdx.x;
    if (idx >= BB * NH * HD) return;
    int p = idx % HD;
    int h = (idx / HD) % NH;
    int b = idx / (HD * NH);
    float c = 0.f;
    for (int tt = 0; tt < NT; tt++) {
        int bid = (b * NT + tt) * NH + h;
        g_S[bid * HD + p] = c;
        c = g_Etot[bid] * c + g_carry[bid * HD + p];
    }
}

// ---------------- pass C: conv + scan + inter-chunk fixup + gate -> fp16 yh ----------------
__global__ void __launch_bounds__(64) k_scanC(const float* __restrict__ conv_w,
                                              const float* __restrict__ conv_b)
{
    const int bid = blockIdx.x;
    const int h = bid % NH;
    const int tt = (bid / NH) % NT;
    const int b = bid / (NH * NT);
    const int p = threadIdx.x;
    const int row0 = b * LL + tt * CHUNKT;
    const int c = h * HD + p;
    const size_t col = DINNER + c;

    __shared__ float se[CHUNKT], sw[CHUNKT], sp[CHUNKT];
    se[p] = g_e[(row0 + p) * NH + h];
    sw[p] = g_w[(row0 + p) * NH + h];
    __syncthreads();
    if (p == 0) {
        float r = 1.f;
        for (int i = 0; i < CHUNKT; i++) { r *= se[i]; sp[i] = r; }
    }
    __syncthreads();

    const float w0 = conv_w[c * 4 + 0], w1 = conv_w[c * 4 + 1];
    const float w2 = conv_w[c * 4 + 2], w3 = conv_w[c * 4 + 3];
    const float cb = conv_b[c];
    const float Sv = g_S[bid * HD + p];

    float x0 = 0.f, x1 = 0.f, x2 = 0.f;
    if (tt > 0) {
        x0 = g_zxcdt[(size_t)(row0 - 3) * DIP + col];
        x1 = g_zxcdt[(size_t)(row0 - 2) * DIP + col];
        x2 = g_zxcdt[(size_t)(row0 - 1) * DIP + col];
    }
    float r = 0.f;
    for (int i = 0; i < CHUNKT; i++) {
        const size_t rowi = (size_t)(row0 + i);
        float xn = g_zxcdt[rowi * DIP + col];
        float a = cb + x0 * w0 + x1 * w1 + x2 * w2 + xn * w3;
        float xs = 1.f / (1.f + expf(-a)) + 0.1f * a;
        r = se[i] * r + sw[i] * xs;
        x0 = x1; x1 = x2; x2 = xn;
        float y = r + Sv * sp[i];
        float z = g_zxcdt[rowi * DIP + c];
        float g = y * (1.f / (1.f + expf(-z)) + 0.1f * z);
        g_yh[rowi * DINNER + c] = __float2half_rn(g);
    }
}

// ---------------- launch ----------------
extern "C" void kernel_launch(void* const* d_in, const int* in_sizes, int n_in,
                              void* d_out, int out_size)
{
    const float* u       = (const float*)d_in[0];
    const float* reward  = (const float*)d_in[1];
    const float* in_w    = (const float*)d_in[2];
    const float* in_b    = (const float*)d_in[3];
    const float* conv_w  = (const float*)d_in[4];
    const float* conv_b  = (const float*)d_in[5];
    const float* bw      = (const float*)d_in[6];
    const float* bb      = (const float*)d_in[7];
    const float* dt_bias = (const float*)d_in[8];
    const float* A_log   = (const float*)d_in[9];
    const float* out_w   = (const float*)d_in[10];
    float* out = (float*)d_out;

    cudaFuncSetAttribute(k_mm, cudaFuncAttributeMaxDynamicSharedMemorySize, SMEM_DYN);

    float* zxcdt;
    __half *uh, *w1h, *w1l, *yh, *w2h, *w2l;
    cudaGetSymbolAddress((void**)&zxcdt, g_zxcdt);
    cudaGetSymbolAddress((void**)&uh, g_uh);
    cudaGetSymbolAddress((void**)&w1h, g_w1h);
    cudaGetSymbolAddress((void**)&w1l, g_w1l);
    cudaGetSymbolAddress((void**)&yh, g_yh);
    cudaGetSymbolAddress((void**)&w2h, g_w2h);
    cudaGetSymbolAddress((void**)&w2l, g_w2l);

    // conversions
    {
        size_t n = (size_t)NROWS * DMODEL;
        k_split_h<<<(unsigned)((n + 255) / 256), 256>>>(u, uh, n);
    }
    {
        size_t n = (size_t)DIP * DMODEL;
        k_split_hl<<<(unsigned)((n + 255) / 256), 256>>>(in_w, w1h, w1l, n);
    }
    {
        size_t n = (size_t)DMODEL * DINNER;
        k_split_hl<<<(unsigned)((n + 255) / 256), 256>>>(out_w, w2h, w2l, n);
    }

    // GEMM1: zxcdt[16384, {0..4095, 4224..4255}] = u @ in_w^T + in_b  (K=1024)
    // grid.x = 33: tiles 0..31 = cols 0..4095, tile 32 remapped to cols 4224..4255
    {
        dim3 grid(33, NROWS / BM);
        k_mm<<<grid, 256, SMEM_DYN>>>(uh, w1h, w1l, in_b, zxcdt, NROWS, DIP, DMODEL, 1);
    }

    k_reduce_bwbb<<<1, 128>>>(bw, bb);
    {
        int n = NROWS * NH;
        k_ew<<<(n + 255) / 256, 256>>>(reward, dt_bias, A_log);
    }
    k_scanA<<<BB * NT * NH, 64>>>(conv_w, conv_b);
    {
        int n = BB * NH * HD;
        k_scanB<<<(n + 255) / 256, 256>>>();
    }
    k_scanC<<<BB * NT * NH, 64>>>(conv_w, conv_b);

    // GEMM2: out[16384, 1024] = y_gated @ out_w^T  (K=2048)
    {
        dim3 grid(DMODEL / BN, NROWS / BM);
        k_mm<<<grid, 256, SMEM_DYN>>>(yh, w2h, w2l, nullptr, out, NROWS, DMODEL, DINNER, 0);
    }
}

// round 12
// speedup vs baseline: 1.4922x; 1.4918x over previous
#include <cuda_runtime.h>
#include <cuda_fp16.h>
#include <math.h>
#include <stdint.h>

// ---------------- problem constants ----------------
#define BB      4
#define LL      4096
#define DMODEL  1024
#define DINNER  2048
#define NH      32
#define HD      64
#define DIP     4256
#define NROWS   (BB*LL)
#define CHUNKT  64
#define NT      (LL/CHUNKT)
#define DTCOL   (DINNER + 2176)   // 4224

// ---------------- GEMM tiling ----------------
#define BM 256
#define BN 128
#define BK 64                     // fp16 K elems per stage (128 bytes per row)
#define STAGES 4
#define A_B     32768             // 256 rows x 128 bytes
#define B_B     16384             // 128 rows x 128 bytes
#define STAGE_B (A_B + B_B)       // 48 KB
#define SMEM_DYN (STAGES*STAGE_B + 1024)

// ---------------- scratch ----------------
__device__ float g_zxcdt[(size_t)NROWS * DIP];
__device__ float g_e[NROWS * NH];
__device__ float g_w[NROWS * NH];
__device__ float g_carry[BB * NT * NH * HD];
__device__ float g_Etot[BB * NT * NH];
__device__ float g_S[BB * NT * NH * HD];
__device__ float g_scal[2];
__device__ __half g_uh[(size_t)NROWS * DMODEL];
__device__ __half g_w1h[(size_t)DIP * DMODEL];
__device__ __half g_yh[(size_t)NROWS * DINNER];
__device__ __half g_w2h[(size_t)DMODEL * DINNER];

// ---------------- helpers ----------------
__device__ __forceinline__ uint32_t s2u(const void* p) {
    uint32_t a;
    asm("{ .reg .u64 t; cvta.to.shared.u64 t, %1; cvt.u32.u64 %0, t; }" : "=r"(a) : "l"(p));
    return a;
}
#define SWZ(x) ((x) ^ (((x) >> 3) & 0x70))

__device__ __forceinline__ void cp16(uint32_t dst, const void* src) {
    asm volatile("cp.async.cg.shared.global [%0], [%1], 16;"
                 :: "r"(dst), "l"(src) : "memory");
}
__device__ __forceinline__ void ldm4(uint32_t* r, uint32_t addr) {
    asm volatile("ldmatrix.sync.aligned.m8n8.x4.shared.b16 {%0,%1,%2,%3}, [%4];"
                 : "=r"(r[0]), "=r"(r[1]), "=r"(r[2]), "=r"(r[3]) : "r"(addr));
}
__device__ __forceinline__ void mma16816(float* d, const uint32_t* a, const uint32_t* b) {
    asm volatile(
        "mma.sync.aligned.m16n8k16.row.col.f32.f16.f16.f32 "
        "{%0,%1,%2,%3}, {%4,%5,%6,%7}, {%8,%9}, {%0,%1,%2,%3};"
        : "+f"(d[0]), "+f"(d[1]), "+f"(d[2]), "+f"(d[3])
        : "r"(a[0]), "r"(a[1]), "r"(a[2]), "r"(a[3]), "r"(b[0]), "r"(b[1]));
}

// ============ HMMA GEMM: C[M,N] = A*B^T (+bias), fp16 in / fp32 acc ============
// A: [M,K] fp16 K-major; B: [N,K] fp16 K-major; C: [M,N] fp32.
// 256 thr, warp grid 4(m) x 2(n), warp tile 64x64, BK=64, 4-stage cp.async.
// remap: if set and blockIdx.x==32, tile covers cols 4224.. (skips dead 4096..4223)
__global__ void __launch_bounds__(256, 1) k_mm(
    const __half* __restrict__ Ah, const __half* __restrict__ Bh,
    const float* __restrict__ bias, float* __restrict__ C,
    int M, int N, int K, int remap)
{
    extern __shared__ char smraw[];
    const uint32_t sb = (s2u(smraw) + 1023u) & ~1023u;
    const int t = threadIdx.x;
    const int wid = t >> 5, lane = t & 31;
    const int wm = wid & 3, wn = wid >> 2;       // warp tile origin (wm*64, wn*64)
    const int m0 = blockIdx.y * BM;
    int n0 = blockIdx.x * BN;
    if (remap && (int)blockIdx.x == 32) n0 = 4224;
    const int nk = K / BK;

    auto load_tile = [&](int kt, int st) {
        const uint32_t base = sb + st * STAGE_B;
        const size_t kof = (size_t)kt * BK;
#pragma unroll
        for (int i = 0; i < 8; i++) {            // A: 256 rows x 8 chunks = 2048 slots
            int id = t + i * 256;
            int r = id >> 3, c = id & 7;
            uint32_t off = SWZ((uint32_t)(r * 128 + c * 16));
            cp16(base + off, Ah + (size_t)(m0 + r) * K + kof + c * 8);
        }
#pragma unroll
        for (int i = 0; i < 4; i++) {            // B: 128 rows x 8 chunks = 1024 slots
            int id = t + i * 256;
            int r = id >> 3, c = id & 7;
            int gn = n0 + r; if (gn >= N) gn = N - 1;   // clamp (junk cols unstored)
            uint32_t off = SWZ((uint32_t)(r * 128 + c * 16));
            cp16(base + A_B + off, Bh + (size_t)gn * K + kof + c * 8);
        }
        asm volatile("cp.async.commit_group;" ::: "memory");
    };

    float acc[4][8][4];
#pragma unroll
    for (int i = 0; i < 4; i++)
#pragma unroll
        for (int j = 0; j < 8; j++)
#pragma unroll
            for (int v = 0; v < 4; v++) acc[i][j][v] = 0.f;

    load_tile(0, 0);
    load_tile(1, 1);
    load_tile(2, 2);

    for (int kt = 0; kt < nk; kt++) {
        asm volatile("cp.async.wait_group 2;" ::: "memory");
        __syncthreads();

        if (kt + 3 < nk) {
            load_tile(kt + 3, (kt + 3) % STAGES);
        } else {
            asm volatile("cp.async.commit_group;" ::: "memory");   // keep group count invariant
        }

        const int st = kt % STAGES;
        const uint32_t abase = sb + st * STAGE_B;
        const uint32_t bbase = abase + A_B;

#pragma unroll
        for (int k16 = 0; k16 < 4; k16++) {
            const int kbyte = k16 * 32;
            uint32_t af[4][4], bf[16];
#pragma unroll
            for (int mt = 0; mt < 4; mt++) {
                int r = wm * 64 + mt * 16 + (lane & 15);
                int cb = kbyte + ((lane >> 4) << 4);
                uint32_t off = SWZ((uint32_t)(r * 128 + cb));
                ldm4(af[mt], abase + off);
            }
#pragma unroll
            for (int bt = 0; bt < 4; bt++) {
                int r = wn * 64 + bt * 16 + (lane & 7) + ((lane & 16) >> 1);
                int cb = kbyte + ((lane & 8) << 1);
                uint32_t off = SWZ((uint32_t)(r * 128 + cb));
                ldm4(&bf[bt * 4], bbase + off);
            }
#pragma unroll
            for (int mt = 0; mt < 4; mt++)
#pragma unroll
                for (int nt = 0; nt < 8; nt++)
                    mma16816(acc[mt][nt], af[mt], &bf[nt * 2]);
        }
        __syncthreads();
    }

    // ---- epilogue: direct float2 stores ----
    const int qr = lane >> 2;
    const int qc = (lane & 3) * 2;
#pragma unroll
    for (int mt = 0; mt < 4; mt++) {
        const int gmA = m0 + wm * 64 + mt * 16 + qr;
#pragma unroll
        for (int nt = 0; nt < 8; nt++) {
            const int gn = n0 + wn * 64 + nt * 8 + qc;
            if (gn < N) {
                float bx = 0.f, by = 0.f;
                if (bias) { bx = bias[gn]; by = bias[gn + 1]; }
                float2 v0 = make_float2(acc[mt][nt][0] + bx, acc[mt][nt][1] + by);
                float2 v1 = make_float2(acc[mt][nt][2] + bx, acc[mt][nt][3] + by);
                *(float2*)(C + (size_t)gmA * N + gn) = v0;
                *(float2*)(C + (size_t)(gmA + 8) * N + gn) = v1;
            }
        }
    }
}

// ---------------- fp32 -> fp16 ----------------
__global__ void k_split_h(const float* __restrict__ s, __half* __restrict__ h, size_t n)
{
    size_t i = (size_t)blockIdx.x * blockDim.x + threadIdx.x;
    if (i >= n) return;
    h[i] = __float2half_rn(s[i]);
}

// ---------------- tiny reductions ----------------
__global__ void k_reduce_bwbb(const float* __restrict__ bw, const float* __restrict__ bb) {
    __shared__ float s1[128], s2[128];
    int t = threadIdx.x;
    s1[t] = bw[t]; s2[t] = bb[t];
    __syncthreads();
    for (int o = 64; o > 0; o >>= 1) {
        if (t < o) { s1[t] += s1[t + o]; s2[t] += s2[t + o]; }
        __syncthreads();
    }
    if (t == 0) { g_scal[0] = s1[0]; g_scal[1] = s2[0]; }
}

// ---------------- e/w precompute ----------------
__global__ void k_ew(const float* __restrict__ reward,
                     const float* __restrict__ dt_bias,
                     const float* __restrict__ A_log)
{
    int idx = blockIdx.x * blockDim.x + threadIdx.x;
    if (idx >= NROWS * NH) return;
    int row = idx / NH;
    int h = idx % NH;
    float raw = g_zxcdt[(size_t)row * DIP + DTCOL + h] + dt_bias[h];
    float dt = (raw > 20.f) ? raw : log1pf(expf(raw));
    float a = -expf(A_log[h]);
    float Bs = reward[row] * g_scal[0] + g_scal[1];
    g_e[idx] = expf(a * dt);
    g_w[idx] = Bs * dt;
}

// ---------------- pass A: fused conv + local scan, carries only ----------------
__global__ void __launch_bounds__(64) k_scanA(const float* __restrict__ conv_w,
                                              const float* __restrict__ conv_b)
{
    const int bid = blockIdx.x;
    const int h = bid % NH;
    const int tt = (bid / NH) % NT;
    const int b = bid / (NH * NT);
    const int p = threadIdx.x;
    const int row0 = b * LL + tt * CHUNKT;
    const int c = h * HD + p;
    const size_t col = DINNER + c;

    __shared__ float se[CHUNKT], sw[CHUNKT];
    se[p] = g_e[(row0 + p) * NH + h];
    sw[p] = g_w[(row0 + p) * NH + h];
    __syncthreads();

    const float w0 = conv_w[c * 4 + 0], w1 = conv_w[c * 4 + 1];
    const float w2 = conv_w[c * 4 + 2], w3 = conv_w[c * 4 + 3];
    const float cb = conv_b[c];

    float x0 = 0.f, x1 = 0.f, x2 = 0.f;
    if (tt > 0) {
        x0 = g_zxcdt[(size_t)(row0 - 3) * DIP + col];
        x1 = g_zxcdt[(size_t)(row0 - 2) * DIP + col];
        x2 = g_zxcdt[(size_t)(row0 - 1) * DIP + col];
    }
    float r = 0.f;
    for (int i = 0; i < CHUNKT; i++) {
        float xn = g_zxcdt[(size_t)(row0 + i) * DIP + col];
        float a = cb + x0 * w0 + x1 * w1 + x2 * w2 + xn * w3;
        float xs = 1.f / (1.f + expf(-a)) + 0.1f * a;
        r = se[i] * r + sw[i] * xs;
        x0 = x1; x1 = x2; x2 = xn;
    }
    g_carry[bid * HD + p] = r;
    if (p == 0) {
        float E = 1.f;
        for (int i = 0; i < CHUNKT; i++) E *= se[i];
        g_Etot[bid] = E;
    }
}

// ---------------- pass B: scan carries across chunks ----------------
__global__ void k_scanB()
{
    int idx = blockIdx.x * blockDim.x + threadIdx.x;
    if (idx >= BB * NH * HD) return;
    int p = idx % HD;
    int h = (idx / HD) % NH;
    int b = idx / (HD * NH);
    float c = 0.f;
    for (int tt = 0; tt < NT; tt++) {
        int bid = (b * NT + tt) * NH + h;
        g_S[bid * HD + p] = c;
        c = g_Etot[bid] * c + g_carry[bid * HD + p];
    }
}

// ---------------- pass C: conv + scan + inter-chunk fixup + gate -> fp16 yh ----------------
__global__ void __launch_bounds__(64) k_scanC(const float* __restrict__ conv_w,
                                              const float* __restrict__ conv_b)
{
    const int bid = blockIdx.x;
    const int h = bid % NH;
    const int tt = (bid / NH) % NT;
    const int b = bid / (NH * NT);
    const int p = threadIdx.x;
    const int row0 = b * LL + tt * CHUNKT;
    const int c = h * HD + p;
    const size_t col = DINNER + c;

    __shared__ float se[CHUNKT], sw[CHUNKT], sp[CHUNKT];
    se[p] = g_e[(row0 + p) * NH + h];
    sw[p] = g_w[(row0 + p) * NH + h];
    __syncthreads();
    if (p == 0) {
        float r = 1.f;
        for (int i = 0; i < CHUNKT; i++) { r *= se[i]; sp[i] = r; }
    }
    __syncthreads();

    const float w0 = conv_w[c * 4 + 0], w1 = conv_w[c * 4 + 1];
    const float w2 = conv_w[c * 4 + 2], w3 = conv_w[c * 4 + 3];
    const float cb = conv_b[c];
    const float Sv = g_S[bid * HD + p];

    float x0 = 0.f, x1 = 0.f, x2 = 0.f;
    if (tt > 0) {
        x0 = g_zxcdt[(size_t)(row0 - 3) * DIP + col];
        x1 = g_zxcdt[(size_t)(row0 - 2) * DIP + col];
        x2 = g_zxcdt[(size_t)(row0 - 1) * DIP + col];
    }
    float r = 0.f;
    for (int i = 0; i < CHUNKT; i++) {
        const size_t rowi = (size_t)(row0 + i);
        float xn = g_zxcdt[rowi * DIP + col];
        float a = cb + x0 * w0 + x1 * w1 + x2 * w2 + xn * w3;
        float xs = 1.f / (1.f + expf(-a)) + 0.1f * a;
        r = se[i] * r + sw[i] * xs;
        x0 = x1; x1 = x2; x2 = xn;
        float y = r + Sv * sp[i];
        float z = g_zxcdt[rowi * DIP + c];
        float g = y * (1.f / (1.f + expf(-z)) + 0.1f * z);
        g_yh[rowi * DINNER + c] = __float2half_rn(g);
    }
}

// ---------------- launch ----------------
extern "C" void kernel_launch(void* const* d_in, const int* in_sizes, int n_in,
                              void* d_out, int out_size)
{
    const float* u       = (const float*)d_in[0];
    const float* reward  = (const float*)d_in[1];
    const float* in_w    = (const float*)d_in[2];
    const float* in_b    = (const float*)d_in[3];
    const float* conv_w  = (const float*)d_in[4];
    const float* conv_b  = (const float*)d_in[5];
    const float* bw      = (const float*)d_in[6];
    const float* bb      = (const float*)d_in[7];
    const float* dt_bias = (const float*)d_in[8];
    const float* A_log   = (const float*)d_in[9];
    const float* out_w   = (const float*)d_in[10];
    float* out = (float*)d_out;

    cudaFuncSetAttribute(k_mm, cudaFuncAttributeMaxDynamicSharedMemorySize, SMEM_DYN);

    float* zxcdt;
    __half *uh, *w1h, *yh, *w2h;
    cudaGetSymbolAddress((void**)&zxcdt, g_zxcdt);
    cudaGetSymbolAddress((void**)&uh, g_uh);
    cudaGetSymbolAddress((void**)&w1h, g_w1h);
    cudaGetSymbolAddress((void**)&yh, g_yh);
    cudaGetSymbolAddress((void**)&w2h, g_w2h);

    // conversions
    {
        size_t n = (size_t)NROWS * DMODEL;
        k_split_h<<<(unsigned)((n + 255) / 256), 256>>>(u, uh, n);
    }
    {
        size_t n = (size_t)DIP * DMODEL;
        k_split_h<<<(unsigned)((n + 255) / 256), 256>>>(in_w, w1h, n);
    }
    {
        size_t n = (size_t)DMODEL * DINNER;
        k_split_h<<<(unsigned)((n + 255) / 256), 256>>>(out_w, w2h, n);
    }

    // GEMM1: zxcdt[16384, {0..4095, 4224..4255}] = u @ in_w^T + in_b  (K=1024)
    {
        dim3 grid(33, NROWS / BM);
        k_mm<<<grid, 256, SMEM_DYN>>>(uh, w1h, in_b, zxcdt, NROWS, DIP, DMODEL, 1);
    }

    k_reduce_bwbb<<<1, 128>>>(bw, bb);
    {
        int n = NROWS * NH;
        k_ew<<<(n + 255) / 256, 256>>>(reward, dt_bias, A_log);
    }
    k_scanA<<<BB * NT * NH, 64>>>(conv_w, conv_b);
    {
        int n = BB * NH * HD;
        k_scanB<<<(n + 255) / 256, 256>>>();
    }
    k_scanC<<<BB * NT * NH, 64>>>(conv_w, conv_b);

    // GEMM2: out[16384, 1024] = y_gated @ out_w^T  (K=2048)
    {
        dim3 grid(DMODEL / BN, NROWS / BM);
        k_mm<<<grid, 256, SMEM_DYN>>>(yh, w2h, nullptr, out, NROWS, DMODEL, DINNER, 0);
    }
}

// round 13
// speedup vs baseline: 1.4922x; 1.0000x over previous
#include <cuda_runtime.h>
#include <cuda_fp16.h>
#include <math.h>
#include <stdint.h>

// ---------------- problem constants ----------------
#define BB      4
#define LL      4096
#define DMODEL  1024
#define DINNER  2048
#define NH      32
#define HD      64
#define DIP     4256
#define NROWS   (BB*LL)
#define CHUNKT  64
#define NT      (LL/CHUNKT)
#define DTCOL   (DINNER + 2176)   // 4224

// ---------------- GEMM tiling ----------------
#define BM 256
#define BN 128
#define BK 64                     // fp16 K elems per stage (128 bytes per row)
#define STAGES 4
#define A_B     32768             // 256 rows x 128 bytes
#define B_B     16384             // 128 rows x 128 bytes
#define STAGE_B (A_B + B_B)       // 48 KB
#define SMEM_DYN (STAGES*STAGE_B + 1024)

// ---------------- scratch ----------------
__device__ float g_zxcdt[(size_t)NROWS * DIP];
__device__ float g_e[NROWS * NH];
__device__ float g_w[NROWS * NH];
__device__ float g_carry[BB * NT * NH * HD];
__device__ float g_Etot[BB * NT * NH];
__device__ float g_S[BB * NT * NH * HD];
__device__ float g_scal[2];
__device__ __half g_uh[(size_t)NROWS * DMODEL];
__device__ __half g_w1h[(size_t)DIP * DMODEL];
__device__ __half g_yh[(size_t)NROWS * DINNER];
__device__ __half g_w2h[(size_t)DMODEL * DINNER];

// ---------------- helpers ----------------
__device__ __forceinline__ uint32_t s2u(const void* p) {
    uint32_t a;
    asm("{ .reg .u64 t; cvta.to.shared.u64 t, %1; cvt.u32.u64 %0, t; }" : "=r"(a) : "l"(p));
    return a;
}
#define SWZ(x) ((x) ^ (((x) >> 3) & 0x70))

__device__ __forceinline__ void cp16(uint32_t dst, const void* src) {
    asm volatile("cp.async.cg.shared.global [%0], [%1], 16;"
                 :: "r"(dst), "l"(src) : "memory");
}
__device__ __forceinline__ void ldm4(uint32_t* r, uint32_t addr) {
    asm volatile("ldmatrix.sync.aligned.m8n8.x4.shared.b16 {%0,%1,%2,%3}, [%4];"
                 : "=r"(r[0]), "=r"(r[1]), "=r"(r[2]), "=r"(r[3]) : "r"(addr));
}
__device__ __forceinline__ void mma16816(float* d, const uint32_t* a, const uint32_t* b) {
    asm volatile(
        "mma.sync.aligned.m16n8k16.row.col.f32.f16.f16.f32 "
        "{%0,%1,%2,%3}, {%4,%5,%6,%7}, {%8,%9}, {%0,%1,%2,%3};"
        : "+f"(d[0]), "+f"(d[1]), "+f"(d[2]), "+f"(d[3])
        : "r"(a[0]), "r"(a[1]), "r"(a[2]), "r"(a[3]), "r"(b[0]), "r"(b[1]));
}

// ============ HMMA GEMM: C[M,N] = A*B^T (+bias), fp16 in / fp32 acc ============
// A: [M,K] fp16 K-major; B: [N,K] fp16 K-major; C: [M,N] fp32.
// 256 thr, warp grid 4(m) x 2(n), warp tile 64x64, BK=64, 4-stage cp.async.
// remap: if set and blockIdx.x==32, tile covers cols 4224.. (skips dead 4096..4223)
__global__ void __launch_bounds__(256, 1) k_mm(
    const __half* __restrict__ Ah, const __half* __restrict__ Bh,
    const float* __restrict__ bias, float* __restrict__ C,
    int M, int N, int K, int remap)
{
    extern __shared__ char smraw[];
    const uint32_t sb = (s2u(smraw) + 1023u) & ~1023u;
    const int t = threadIdx.x;
    const int wid = t >> 5, lane = t & 31;
    const int wm = wid & 3, wn = wid >> 2;       // warp tile origin (wm*64, wn*64)
    const int m0 = blockIdx.y * BM;
    int n0 = blockIdx.x * BN;
    if (remap && (int)blockIdx.x == 32) n0 = 4224;
    const int nk = K / BK;

    auto load_tile = [&](int kt, int st) {
        const uint32_t base = sb + st * STAGE_B;
        const size_t kof = (size_t)kt * BK;
#pragma unroll
        for (int i = 0; i < 8; i++) {            // A: 256 rows x 8 chunks = 2048 slots
            int id = t + i * 256;
            int r = id >> 3, c = id & 7;
            uint32_t off = SWZ((uint32_t)(r * 128 + c * 16));
            cp16(base + off, Ah + (size_t)(m0 + r) * K + kof + c * 8);
        }
#pragma unroll
        for (int i = 0; i < 4; i++) {            // B: 128 rows x 8 chunks = 1024 slots
            int id = t + i * 256;
            int r = id >> 3, c = id & 7;
            int gn = n0 + r; if (gn >= N) gn = N - 1;   // clamp (junk cols unstored)
            uint32_t off = SWZ((uint32_t)(r * 128 + c * 16));
            cp16(base + A_B + off, Bh + (size_t)gn * K + kof + c * 8);
        }
        asm volatile("cp.async.commit_group;" ::: "memory");
    };

    float acc[4][8][4];
#pragma unroll
    for (int i = 0; i < 4; i++)
#pragma unroll
        for (int j = 0; j < 8; j++)
#pragma unroll
            for (int v = 0; v < 4; v++) acc[i][j][v] = 0.f;

    load_tile(0, 0);
    load_tile(1, 1);
    load_tile(2, 2);

    for (int kt = 0; kt < nk; kt++) {
        asm volatile("cp.async.wait_group 2;" ::: "memory");
        __syncthreads();

        if (kt + 3 < nk) {
            load_tile(kt + 3, (kt + 3) % STAGES);
        } else {
            asm volatile("cp.async.commit_group;" ::: "memory");   // keep group count invariant
        }

        const int st = kt % STAGES;
        const uint32_t abase = sb + st * STAGE_B;
        const uint32_t bbase = abase + A_B;

#pragma unroll
        for (int k16 = 0; k16 < 4; k16++) {
            const int kbyte = k16 * 32;
            uint32_t af[4][4], bf[16];
#pragma unroll
            for (int mt = 0; mt < 4; mt++) {
                int r = wm * 64 + mt * 16 + (lane & 15);
                int cb = kbyte + ((lane >> 4) << 4);
                uint32_t off = SWZ((uint32_t)(r * 128 + cb));
                ldm4(af[mt], abase + off);
            }
#pragma unroll
            for (int bt = 0; bt < 4; bt++) {
                int r = wn * 64 + bt * 16 + (lane & 7) + ((lane & 16) >> 1);
                int cb = kbyte + ((lane & 8) << 1);
                uint32_t off = SWZ((uint32_t)(r * 128 + cb));
                ldm4(&bf[bt * 4], bbase + off);
            }
#pragma unroll
            for (int mt = 0; mt < 4; mt++)
#pragma unroll
                for (int nt = 0; nt < 8; nt++)
                    mma16816(acc[mt][nt], af[mt], &bf[nt * 2]);
        }
        __syncthreads();
    }

    // ---- epilogue: direct float2 stores ----
    const int qr = lane >> 2;
    const int qc = (lane & 3) * 2;
#pragma unroll
    for (int mt = 0; mt < 4; mt++) {
        const int gmA = m0 + wm * 64 + mt * 16 + qr;
#pragma unroll
        for (int nt = 0; nt < 8; nt++) {
            const int gn = n0 + wn * 64 + nt * 8 + qc;
            if (gn < N) {
                float bx = 0.f, by = 0.f;
                if (bias) { bx = bias[gn]; by = bias[gn + 1]; }
                float2 v0 = make_float2(acc[mt][nt][0] + bx, acc[mt][nt][1] + by);
                float2 v1 = make_float2(acc[mt][nt][2] + bx, acc[mt][nt][3] + by);
                *(float2*)(C + (size_t)gmA * N + gn) = v0;
                *(float2*)(C + (size_t)(gmA + 8) * N + gn) = v1;
            }
        }
    }
}

// ---------------- fp32 -> fp16 ----------------
__global__ void k_split_h(const float* __restrict__ s, __half* __restrict__ h, size_t n)
{
    size_t i = (size_t)blockIdx.x * blockDim.x + threadIdx.x;
    if (i >= n) return;
    h[i] = __float2half_rn(s[i]);
}

// ---------------- tiny reductions ----------------
__global__ void k_reduce_bwbb(const float* __restrict__ bw, const float* __restrict__ bb) {
    __shared__ float s1[128], s2[128];
    int t = threadIdx.x;
    s1[t] = bw[t]; s2[t] = bb[t];
    __syncthreads();
    for (int o = 64; o > 0; o >>= 1) {
        if (t < o) { s1[t] += s1[t + o]; s2[t] += s2[t + o]; }
        __syncthreads();
    }
    if (t == 0) { g_scal[0] = s1[0]; g_scal[1] = s2[0]; }
}

// ---------------- e/w precompute ----------------
__global__ void k_ew(const float* __restrict__ reward,
                     const float* __restrict__ dt_bias,
                     const float* __restrict__ A_log)
{
    int idx = blockIdx.x * blockDim.x + threadIdx.x;
    if (idx >= NROWS * NH) return;
    int row = idx / NH;
    int h = idx % NH;
    float raw = g_zxcdt[(size_t)row * DIP + DTCOL + h] + dt_bias[h];
    float dt = (raw > 20.f) ? raw : log1pf(expf(raw));
    float a = -expf(A_log[h]);
    float Bs = reward[row] * g_scal[0] + g_scal[1];
    g_e[idx] = expf(a * dt);
    g_w[idx] = Bs * dt;
}

// ---------------- pass A: fused conv + local scan, carries only ----------------
__global__ void __launch_bounds__(64) k_scanA(const float* __restrict__ conv_w,
                                              const float* __restrict__ conv_b)
{
    const int bid = blockIdx.x;
    const int h = bid % NH;
    const int tt = (bid / NH) % NT;
    const int b = bid / (NH * NT);
    const int p = threadIdx.x;
    const int row0 = b * LL + tt * CHUNKT;
    const int c = h * HD + p;
    const size_t col = DINNER + c;

    __shared__ float se[CHUNKT], sw[CHUNKT];
    se[p] = g_e[(row0 + p) * NH + h];
    sw[p] = g_w[(row0 + p) * NH + h];
    __syncthreads();

    const float w0 = conv_w[c * 4 + 0], w1 = conv_w[c * 4 + 1];
    const float w2 = conv_w[c * 4 + 2], w3 = conv_w[c * 4 + 3];
    const float cb = conv_b[c];

    float x0 = 0.f, x1 = 0.f, x2 = 0.f;
    if (tt > 0) {
        x0 = g_zxcdt[(size_t)(row0 - 3) * DIP + col];
        x1 = g_zxcdt[(size_t)(row0 - 2) * DIP + col];
        x2 = g_zxcdt[(size_t)(row0 - 1) * DIP + col];
    }
    float r = 0.f;
    for (int i = 0; i < CHUNKT; i++) {
        float xn = g_zxcdt[(size_t)(row0 + i) * DIP + col];
        float a = cb + x0 * w0 + x1 * w1 + x2 * w2 + xn * w3;
        float xs = 1.f / (1.f + expf(-a)) + 0.1f * a;
        r = se[i] * r + sw[i] * xs;
        x0 = x1; x1 = x2; x2 = xn;
    }
    g_carry[bid * HD + p] = r;
    if (p == 0) {
        float E = 1.f;
        for (int i = 0; i < CHUNKT; i++) E *= se[i];
        g_Etot[bid] = E;
    }
}

// ---------------- pass B: scan carries across chunks ----------------
__global__ void k_scanB()
{
    int idx = blockIdx.x * blockDim.x + threadIdx.x;
    if (idx >= BB * NH * HD) return;
    int p = idx % HD;
    int h = (idx / HD) % NH;
    int b = idx / (HD * NH);
    float c = 0.f;
    for (int tt = 0; tt < NT; tt++) {
        int bid = (b * NT + tt) * NH + h;
        g_S[bid * HD + p] = c;
        c = g_Etot[bid] * c + g_carry[bid * HD + p];
    }
}

// ---------------- pass C: conv + scan + inter-chunk fixup + gate -> fp16 yh ----------------
__global__ void __launch_bounds__(64) k_scanC(const float* __restrict__ conv_w,
                                              const float* __restrict__ conv_b)
{
    const int bid = blockIdx.x;
    const int h = bid % NH;
    const int tt = (bid / NH) % NT;
    const int b = bid / (NH * NT);
    const int p = threadIdx.x;
    const int row0 = b * LL + tt * CHUNKT;
    const int c = h * HD + p;
    const size_t col = DINNER + c;

    __shared__ float se[CHUNKT], sw[CHUNKT], sp[CHUNKT];
    se[p] = g_e[(row0 + p) * NH + h];
    sw[p] = g_w[(row0 + p) * NH + h];
    __syncthreads();
    if (p == 0) {
        float r = 1.f;
        for (int i = 0; i < CHUNKT; i++) { r *= se[i]; sp[i] = r; }
    }
    __syncthreads();

    const float w0 = conv_w[c * 4 + 0], w1 = conv_w[c * 4 + 1];
    const float w2 = conv_w[c * 4 + 2], w3 = conv_w[c * 4 + 3];
    const float cb = conv_b[c];
    const float Sv = g_S[bid * HD + p];

    float x0 = 0.f, x1 = 0.f, x2 = 0.f;
    if (tt > 0) {
        x0 = g_zxcdt[(size_t)(row0 - 3) * DIP + col];
        x1 = g_zxcdt[(size_t)(row0 - 2) * DIP + col];
        x2 = g_zxcdt[(size_t)(row0 - 1) * DIP + col];
    }
    float r = 0.f;
    for (int i = 0; i < CHUNKT; i++) {
        const size_t rowi = (size_t)(row0 + i);
        float xn = g_zxcdt[rowi * DIP + col];
        float a = cb + x0 * w0 + x1 * w1 + x2 * w2 + xn * w3;
        float xs = 1.f / (1.f + expf(-a)) + 0.1f * a;
        r = se[i] * r + sw[i] * xs;
        x0 = x1; x1 = x2; x2 = xn;
        float y = r + Sv * sp[i];
        float z = g_zxcdt[rowi * DIP + c];
        float g = y * (1.f / (1.f + expf(-z)) + 0.1f * z);
        g_yh[rowi * DINNER + c] = __float2half_rn(g);
    }
}

// ---------------- launch ----------------
extern "C" void kernel_launch(void* const* d_in, const int* in_sizes, int n_in,
                              void* d_out, int out_size)
{
    const float* u       = (const float*)d_in[0];
    const float* reward  = (const float*)d_in[1];
    const float* in_w    = (const float*)d_in[2];
    const float* in_b    = (const float*)d_in[3];
    const float* conv_w  = (const float*)d_in[4];
    const float* conv_b  = (const float*)d_in[5];
    const float* bw      = (const float*)d_in[6];
    const float* bb      = (const float*)d_in[7];
    const float* dt_bias = (const float*)d_in[8];
    const float* A_log   = (const float*)d_in[9];
    const float* out_w   = (const float*)d_in[10];
    float* out = (float*)d_out;

    cudaFuncSetAttribute(k_mm, cudaFuncAttributeMaxDynamicSharedMemorySize, SMEM_DYN);

    float* zxcdt;
    __half *uh, *w1h, *yh, *w2h;
    cudaGetSymbolAddress((void**)&zxcdt, g_zxcdt);
    cudaGetSymbolAddress((void**)&uh, g_uh);
    cudaGetSymbolAddress((void**)&w1h, g_w1h);
    cudaGetSymbolAddress((void**)&yh, g_yh);
    cudaGetSymbolAddress((void**)&w2h, g_w2h);

    // conversions
    {
        size_t n = (size_t)NROWS * DMODEL;
        k_split_h<<<(unsigned)((n + 255) / 256), 256>>>(u, uh, n);
    }
    {
        size_t n = (size_t)DIP * DMODEL;
        k_split_h<<<(unsigned)((n + 255) / 256), 256>>>(in_w, w1h, n);
    }
    {
        size_t n = (size_t)DMODEL * DINNER;
        k_split_h<<<(unsigned)((n + 255) / 256), 256>>>(out_w, w2h, n);
    }

    // GEMM1: zxcdt[16384, {0..4095, 4224..4255}] = u @ in_w^T + in_b  (K=1024)
    {
        dim3 grid(33, NROWS / BM);
        k_mm<<<grid, 256, SMEM_DYN>>>(uh, w1h, in_b, zxcdt, NROWS, DIP, DMODEL, 1);
    }

    k_reduce_bwbb<<<1, 128>>>(bw, bb);
    {
        int n = NROWS * NH;
        k_ew<<<(n + 255) / 256, 256>>>(reward, dt_bias, A_log);
    }
    k_scanA<<<BB * NT * NH, 64>>>(conv_w, conv_b);
    {
        int n = BB * NH * HD;
        k_scanB<<<(n + 255) / 256, 256>>>();
    }
    k_scanC<<<BB * NT * NH, 64>>>(conv_w, conv_b);

    // GEMM2: out[16384, 1024] = y_gated @ out_w^T  (K=2048)
    {
        dim3 grid(DMODEL / BN, NROWS / BM);
        k_mm<<<grid, 256, SMEM_DYN>>>(yh, w2h, nullptr, out, NROWS, DMODEL, DINNER, 0);
    }
}

// round 14
// speedup vs baseline: 1.5024x; 1.0068x over previous
#include <cuda_runtime.h>
#include <cuda_fp16.h>
#include <math.h>
#include <stdint.h>

// ---------------- problem constants ----------------
#define BB      4
#define LL      4096
#define DMODEL  1024
#define DINNER  2048
#define NH      32
#define HD      64
#define DIP     4256
#define NROWS   (BB*LL)
#define CHUNKT  64
#define NT      (LL/CHUNKT)

// ---------------- GEMM tiling ----------------
#define BM 256
#define BN 128
#define BK 64                     // fp16 K elems per stage (128 bytes per row)
#define STAGES 4
#define A_B     32768             // 256 rows x 128 bytes
#define B_B     16384             // 128 rows x 128 bytes
#define STAGE_B (A_B + B_B)       // 48 KB
#define SMEM_DYN (STAGES*STAGE_B + 1024)

// ---------------- scratch ----------------
__device__ float g_z[(size_t)NROWS * DINNER];     // gate pre-activation
__device__ float g_x[(size_t)NROWS * DINNER];     // conv input (pre-conv xC x-part)
__device__ float g_dt[(size_t)NROWS * 32];        // dt raw
__device__ float g_e[NROWS * NH];
__device__ float g_w[NROWS * NH];
__device__ float g_carry[BB * NT * NH * HD];
__device__ float g_Etot[BB * NT * NH];
__device__ float g_S[BB * NT * NH * HD];
__device__ float g_scal[2];
__device__ __half g_uh[(size_t)NROWS * DMODEL];
__device__ __half g_w1h[(size_t)DIP * DMODEL];
__device__ __half g_yh[(size_t)NROWS * DINNER];
__device__ __half g_w2h[(size_t)DMODEL * DINNER];

// ---------------- helpers ----------------
__device__ __forceinline__ uint32_t s2u(const void* p) {
    uint32_t a;
    asm("{ .reg .u64 t; cvta.to.shared.u64 t, %1; cvt.u32.u64 %0, t; }" : "=r"(a) : "l"(p));
    return a;
}
#define SWZ(x) ((x) ^ (((x) >> 3) & 0x70))

__device__ __forceinline__ void cp16(uint32_t dst, const void* src) {
    asm volatile("cp.async.cg.shared.global [%0], [%1], 16;"
                 :: "r"(dst), "l"(src) : "memory");
}
__device__ __forceinline__ void ldm4(uint32_t* r, uint32_t addr) {
    asm volatile("ldmatrix.sync.aligned.m8n8.x4.shared.b16 {%0,%1,%2,%3}, [%4];"
                 : "=r"(r[0]), "=r"(r[1]), "=r"(r[2]), "=r"(r[3]) : "r"(addr));
}
__device__ __forceinline__ void mma16816(float* d, const uint32_t* a, const uint32_t* b) {
    asm volatile(
        "mma.sync.aligned.m16n8k16.row.col.f32.f16.f16.f32 "
        "{%0,%1,%2,%3}, {%4,%5,%6,%7}, {%8,%9}, {%0,%1,%2,%3};"
        : "+f"(d[0]), "+f"(d[1]), "+f"(d[2]), "+f"(d[3])
        : "r"(a[0]), "r"(a[1]), "r"(a[2]), "r"(a[3]), "r"(b[0]), "r"(b[1]));
}

// ============ HMMA GEMM: C = A*B^T (+bias), fp16 in / fp32 acc ============
// A: [M,K] fp16 K-major; B: [N,K] fp16 K-major.
// remap=1 (GEMM1): output routed per tile: n0<2048 -> Cz, n0<4096 -> Cx (col-2048),
//   tile 32 (remapped to DIP col 4224) -> Cdt (pitch 32). bias indexed in DIP space.
// remap=0: single output Cz with pitch N.
__global__ void __launch_bounds__(256, 1) k_mm(
    const __half* __restrict__ Ah, const __half* __restrict__ Bh,
    const float* __restrict__ bias,
    float* __restrict__ Cz, float* __restrict__ Cx, float* __restrict__ Cdt,
    int M, int N, int K, int remap)
{
    extern __shared__ char smraw[];
    const uint32_t sb = (s2u(smraw) + 1023u) & ~1023u;
    const int t = threadIdx.x;
    const int wid = t >> 5, lane = t & 31;
    const int wm = wid & 3, wn = wid >> 2;       // warp tile origin (wm*64, wn*64)
    const int m0 = blockIdx.y * BM;
    int n0 = blockIdx.x * BN;
    if (remap && (int)blockIdx.x == 32) n0 = 4224;
    const int nk = K / BK;

    // per-block output routing
    float* outp; int pitch, coff;
    if (remap) {
        if (n0 < 2048)      { outp = Cz;  pitch = 2048; coff = 0; }
        else if (n0 < 4096) { outp = Cx;  pitch = 2048; coff = 2048; }
        else                { outp = Cdt; pitch = 32;   coff = 4224; }
    } else { outp = Cz; pitch = N; coff = 0; }

    auto load_tile = [&](int kt, int st) {
        const uint32_t base = sb + st * STAGE_B;
        const size_t kof = (size_t)kt * BK;
#pragma unroll
        for (int i = 0; i < 8; i++) {            // A: 256 rows x 8 chunks
            int id = t + i * 256;
            int r = id >> 3, c = id & 7;
            uint32_t off = SWZ((uint32_t)(r * 128 + c * 16));
            cp16(base + off, Ah + (size_t)(m0 + r) * K + kof + c * 8);
        }
#pragma unroll
        for (int i = 0; i < 4; i++) {            // B: 128 rows x 8 chunks
            int id = t + i * 256;
            int r = id >> 3, c = id & 7;
            int gn = n0 + r; if (gn >= N) gn = N - 1;   // clamp (junk cols unstored)
            uint32_t off = SWZ((uint32_t)(r * 128 + c * 16));
            cp16(base + A_B + off, Bh + (size_t)gn * K + kof + c * 8);
        }
        asm volatile("cp.async.commit_group;" ::: "memory");
    };

    float acc[4][8][4];
#pragma unroll
    for (int i = 0; i < 4; i++)
#pragma unroll
        for (int j = 0; j < 8; j++)
#pragma unroll
            for (int v = 0; v < 4; v++) acc[i][j][v] = 0.f;

    load_tile(0, 0);
    load_tile(1, 1);
    load_tile(2, 2);

    for (int kt = 0; kt < nk; kt++) {
        asm volatile("cp.async.wait_group 2;" ::: "memory");
        __syncthreads();   // all warps done with stage (kt-1)%4 before it is overwritten below

        if (kt + 3 < nk) {
            load_tile(kt + 3, (kt + 3) % STAGES);
        } else {
            asm volatile("cp.async.commit_group;" ::: "memory");   // keep group count invariant
        }

        const int st = kt % STAGES;
        const uint32_t abase = sb + st * STAGE_B;
        const uint32_t bbase = abase + A_B;

#pragma unroll
        for (int k16 = 0; k16 < 4; k16++) {
            const int kbyte = k16 * 32;
            uint32_t af[4][4], bf[16];
#pragma unroll
            for (int mt = 0; mt < 4; mt++) {
                int r = wm * 64 + mt * 16 + (lane & 15);
                int cb = kbyte + ((lane >> 4) << 4);
                uint32_t off = SWZ((uint32_t)(r * 128 + cb));
                ldm4(af[mt], abase + off);
            }
#pragma unroll
            for (int bt = 0; bt < 4; bt++) {
                int r = wn * 64 + bt * 16 + (lane & 7) + ((lane & 16) >> 1);
                int cb = kbyte + ((lane & 8) << 1);
                uint32_t off = SWZ((uint32_t)(r * 128 + cb));
                ldm4(&bf[bt * 4], bbase + off);
            }
#pragma unroll
            for (int mt = 0; mt < 4; mt++)
#pragma unroll
                for (int nt = 0; nt < 8; nt++)
                    mma16816(acc[mt][nt], af[mt], &bf[nt * 2]);
        }
        // no trailing barrier: next iteration's top barrier protects stage reuse
    }

    // ---- epilogue: routed float2 stores ----
    const int qr = lane >> 2;
    const int qc = (lane & 3) * 2;
#pragma unroll
    for (int mt = 0; mt < 4; mt++) {
        const int gmA = m0 + wm * 64 + mt * 16 + qr;
#pragma unroll
        for (int nt = 0; nt < 8; nt++) {
            const int gn = n0 + wn * 64 + nt * 8 + qc;     // global col (DIP space for remap)
            const int lc = gn - coff;
            if (lc < pitch) {
                float bx = 0.f, by = 0.f;
                if (bias) { bx = bias[gn]; by = bias[gn + 1]; }
                float2 v0 = make_float2(acc[mt][nt][0] + bx, acc[mt][nt][1] + by);
                float2 v1 = make_float2(acc[mt][nt][2] + bx, acc[mt][nt][3] + by);
                *(float2*)(outp + (size_t)gmA * pitch + lc) = v0;
                *(float2*)(outp + (size_t)(gmA + 8) * pitch + lc) = v1;
            }
        }
    }
}

// ---------------- fp32 -> fp16 ----------------
__global__ void k_split_h(const float* __restrict__ s, __half* __restrict__ h, size_t n)
{
    size_t i = (size_t)blockIdx.x * blockDim.x + threadIdx.x;
    if (i >= n) return;
    h[i] = __float2half_rn(s[i]);
}

// ---------------- tiny reductions ----------------
__global__ void k_reduce_bwbb(const float* __restrict__ bw, const float* __restrict__ bb) {
    __shared__ float s1[128], s2[128];
    int t = threadIdx.x;
    s1[t] = bw[t]; s2[t] = bb[t];
    __syncthreads();
    for (int o = 64; o > 0; o >>= 1) {
        if (t < o) { s1[t] += s1[t + o]; s2[t] += s2[t + o]; }
        __syncthreads();
    }
    if (t == 0) { g_scal[0] = s1[0]; g_scal[1] = s2[0]; }
}

// ---------------- e/w precompute (dense dt reads) ----------------
__global__ void k_ew(const float* __restrict__ reward,
                     const float* __restrict__ dt_bias,
                     const float* __restrict__ A_log)
{
    int idx = blockIdx.x * blockDim.x + threadIdx.x;
    if (idx >= NROWS * NH) return;
    int row = idx / NH;
    int h = idx % NH;
    float raw = g_dt[(size_t)row * 32 + h] + dt_bias[h];
    float dt = (raw > 20.f) ? raw : log1pf(expf(raw));
    float a = -expf(A_log[h]);
    float Bs = reward[row] * g_scal[0] + g_scal[1];
    g_e[idx] = expf(a * dt);
    g_w[idx] = Bs * dt;
}

// ---------------- pass A: fused conv + local scan, carries only ----------------
__global__ void __launch_bounds__(64) k_scanA(const float* __restrict__ conv_w,
                                              const float* __restrict__ conv_b)
{
    const int bid = blockIdx.x;
    const int h = bid % NH;
    const int tt = (bid / NH) % NT;
    const int b = bid / (NH * NT);
    const int p = threadIdx.x;
    const int row0 = b * LL + tt * CHUNKT;
    const int c = h * HD + p;

    __shared__ float se[CHUNKT], sw[CHUNKT];
    se[p] = g_e[(row0 + p) * NH + h];
    sw[p] = g_w[(row0 + p) * NH + h];
    __syncthreads();

    const float w0 = conv_w[c * 4 + 0], w1 = conv_w[c * 4 + 1];
    const float w2 = conv_w[c * 4 + 2], w3 = conv_w[c * 4 + 3];
    const float cb = conv_b[c];

    float x0 = 0.f, x1 = 0.f, x2 = 0.f;
    if (tt > 0) {
        x0 = g_x[(size_t)(row0 - 3) * DINNER + c];
        x1 = g_x[(size_t)(row0 - 2) * DINNER + c];
        x2 = g_x[(size_t)(row0 - 1) * DINNER + c];
    }
    float r = 0.f;
    for (int i = 0; i < CHUNKT; i++) {
        float xn = g_x[(size_t)(row0 + i) * DINNER + c];
        float a = cb + x0 * w0 + x1 * w1 + x2 * w2 + xn * w3;
        float xs = 1.f / (1.f + expf(-a)) + 0.1f * a;
        r = se[i] * r + sw[i] * xs;
        x0 = x1; x1 = x2; x2 = xn;
    }
    g_carry[bid * HD + p] = r;
    if (p == 0) {
        float E = 1.f;
        for (int i = 0; i < CHUNKT; i++) E *= se[i];
        g_Etot[bid] = E;
    }
}

// ---------------- pass B: scan carries across chunks ----------------
__global__ void k_scanB()
{
    int idx = blockIdx.x * blockDim.x + threadIdx.x;
    if (idx >= BB * NH * HD) return;
    int p = idx % HD;
    int h = (idx / HD) % NH;
    int b = idx / (HD * NH);
    float c = 0.f;
    for (int tt = 0; tt < NT; tt++) {
        int bid = (b * NT + tt) * NH + h;
        g_S[bid * HD + p] = c;
        c = g_Etot[bid] * c + g_carry[bid * HD + p];
    }
}

// ---------------- pass C: conv + scan + inter-chunk fixup + gate -> fp16 yh ----------------
__global__ void __launch_bounds__(64) k_scanC(const float* __restrict__ conv_w,
                                              const float* __restrict__ conv_b)
{
    const int bid = blockIdx.x;
    const int h = bid % NH;
    const int tt = (bid / NH) % NT;
    const int b = bid / (NH * NT);
    const int p = threadIdx.x;
    const int row0 = b * LL + tt * CHUNKT;
    const int c = h * HD + p;

    __shared__ float se[CHUNKT], sw[CHUNKT], sp[CHUNKT];
    se[p] = g_e[(row0 + p) * NH + h];
    sw[p] = g_w[(row0 + p) * NH + h];
    __syncthreads();
    if (p == 0) {
        float r = 1.f;
        for (int i = 0; i < CHUNKT; i++) { r *= se[i]; sp[i] = r; }
    }
    __syncthreads();

    const float w0 = conv_w[c * 4 + 0], w1 = conv_w[c * 4 + 1];
    const float w2 = conv_w[c * 4 + 2], w3 = conv_w[c * 4 + 3];
    const float cb = conv_b[c];
    const float Sv = g_S[bid * HD + p];

    float x0 = 0.f, x1 = 0.f, x2 = 0.f;
    if (tt > 0) {
        x0 = g_x[(size_t)(row0 - 3) * DINNER + c];
        x1 = g_x[(size_t)(row0 - 2) * DINNER + c];
        x2 = g_x[(size_t)(row0 - 1) * DINNER + c];
    }
    float r = 0.f;
    for (int i = 0; i < CHUNKT; i++) {
        const size_t rowi = (size_t)(row0 + i);
        float xn = g_x[rowi * DINNER + c];
        float a = cb + x0 * w0 + x1 * w1 + x2 * w2 + xn * w3;
        float xs = 1.f / (1.f + expf(-a)) + 0.1f * a;
        r = se[i] * r + sw[i] * xs;
        x0 = x1; x1 = x2; x2 = xn;
        float y = r + Sv * sp[i];
        float z = g_z[rowi * DINNER + c];
        float g = y * (1.f / (1.f + expf(-z)) + 0.1f * z);
        g_yh[rowi * DINNER + c] = __float2half_rn(g);
    }
}

// ---------------- launch ----------------
extern "C" void kernel_launch(void* const* d_in, const int* in_sizes, int n_in,
                              void* d_out, int out_size)
{
    const float* u       = (const float*)d_in[0];
    const float* reward  = (const float*)d_in[1];
    const float* in_w    = (const float*)d_in[2];
    const float* in_b    = (const float*)d_in[3];
    const float* conv_w  = (const float*)d_in[4];
    const float* conv_b  = (const float*)d_in[5];
    const float* bw      = (const float*)d_in[6];
    const float* bb      = (const float*)d_in[7];
    const float* dt_bias = (const float*)d_in[8];
    const float* A_log   = (const float*)d_in[9];
    const float* out_w   = (const float*)d_in[10];
    float* out = (float*)d_out;

    cudaFuncSetAttribute(k_mm, cudaFuncAttributeMaxDynamicSharedMemorySize, SMEM_DYN);

    float *zp, *xp, *dtp;
    __half *uh, *w1h, *yh, *w2h;
    cudaGetSymbolAddress((void**)&zp, g_z);
    cudaGetSymbolAddress((void**)&xp, g_x);
    cudaGetSymbolAddress((void**)&dtp, g_dt);
    cudaGetSymbolAddress((void**)&uh, g_uh);
    cudaGetSymbolAddress((void**)&w1h, g_w1h);
    cudaGetSymbolAddress((void**)&yh, g_yh);
    cudaGetSymbolAddress((void**)&w2h, g_w2h);

    // conversions
    {
        size_t n = (size_t)NROWS * DMODEL;
        k_split_h<<<(unsigned)((n + 255) / 256), 256>>>(u, uh, n);
    }
    {
        size_t n = (size_t)DIP * DMODEL;
        k_split_h<<<(unsigned)((n + 255) / 256), 256>>>(in_w, w1h, n);
    }
    {
        size_t n = (size_t)DMODEL * DINNER;
        k_split_h<<<(unsigned)((n + 255) / 256), 256>>>(out_w, w2h, n);
    }

    // GEMM1: routed outputs z/x/dt  (M=16384, K=1024; tile 32 remapped to DIP cols 4224..)
    {
        dim3 grid(33, NROWS / BM);
        k_mm<<<grid, 256, SMEM_DYN>>>(uh, w1h, in_b, zp, xp, dtp, NROWS, DIP, DMODEL, 1);
    }

    k_reduce_bwbb<<<1, 128>>>(bw, bb);
    {
        int n = NROWS * NH;
        k_ew<<<(n + 255) / 256, 256>>>(reward, dt_bias, A_log);
    }
    k_scanA<<<BB * NT * NH, 64>>>(conv_w, conv_b);
    {
        int n = BB * NH * HD;
        k_scanB<<<(n + 255) / 256, 256>>>();
    }
    k_scanC<<<BB * NT * NH, 64>>>(conv_w, conv_b);

    // GEMM2: out[16384, 1024] = y_gated @ out_w^T  (K=2048)
    {
        dim3 grid(DMODEL / BN, NROWS / BM);
        k_mm<<<grid, 256, SMEM_DYN>>>(yh, w2h, nullptr, out, out, out, NROWS, DMODEL, DINNER, 0);
    }
}

// round 15
// speedup vs baseline: 1.5175x; 1.0101x over previous
#include <cuda_runtime.h>
#include <cuda_fp16.h>
#include <math.h>
#include <stdint.h>

// ---------------- problem constants ----------------
#define BB      4
#define LL      4096
#define DMODEL  1024
#define DINNER  2048
#define NH      32
#define HD      64
#define DIP     4256
#define NROWS   (BB*LL)
#define CHUNKT  64
#define NT      (LL/CHUNKT)

// ---------------- GEMM tiling ----------------
#define BM 128
#define BN 128
#define BK 64                     // fp16 K elems per stage (128 bytes per row)
#define STAGES 3
#define A_B     16384             // 128 rows x 128 bytes
#define B_B     16384
#define STAGE_B (A_B + B_B)       // 32 KB
#define SMEM_DYN (STAGES*STAGE_B + 1024)

// ---------------- scratch ----------------
__device__ float  g_z[(size_t)NROWS * DINNER];    // gate pre-activation (fp32)
__device__ __half g_xh[(size_t)NROWS * DINNER];   // conv input (fp16)
__device__ float  g_dt[(size_t)NROWS * 32];       // dt raw
__device__ float  g_e[NROWS * NH];
__device__ float  g_w[NROWS * NH];
__device__ float  g_carry[BB * NT * NH * HD];
__device__ float  g_Etot[BB * NT * NH];
__device__ float  g_S[BB * NT * NH * HD];
__device__ float  g_scal[2];
__device__ __half g_uh[(size_t)NROWS * DMODEL];
__device__ __half g_w1h[(size_t)DIP * DMODEL];
__device__ __half g_yh[(size_t)NROWS * DINNER];
__device__ __half g_w2h[(size_t)DMODEL * DINNER];

// ---------------- helpers ----------------
__device__ __forceinline__ uint32_t s2u(const void* p) {
    uint32_t a;
    asm("{ .reg .u64 t; cvta.to.shared.u64 t, %1; cvt.u32.u64 %0, t; }" : "=r"(a) : "l"(p));
    return a;
}
#define SWZ(x) ((x) ^ (((x) >> 3) & 0x70))

__device__ __forceinline__ void cp16(uint32_t dst, const void* src) {
    asm volatile("cp.async.cg.shared.global [%0], [%1], 16;"
                 :: "r"(dst), "l"(src) : "memory");
}
__device__ __forceinline__ void ldm4(uint32_t* r, uint32_t addr) {
    asm volatile("ldmatrix.sync.aligned.m8n8.x4.shared.b16 {%0,%1,%2,%3}, [%4];"
                 : "=r"(r[0]), "=r"(r[1]), "=r"(r[2]), "=r"(r[3]) : "r"(addr));
}
__device__ __forceinline__ void mma16816(float* d, const uint32_t* a, const uint32_t* b) {
    asm volatile(
        "mma.sync.aligned.m16n8k16.row.col.f32.f16.f16.f32 "
        "{%0,%1,%2,%3}, {%4,%5,%6,%7}, {%8,%9}, {%0,%1,%2,%3};"
        : "+f"(d[0]), "+f"(d[1]), "+f"(d[2]), "+f"(d[3])
        : "r"(a[0]), "r"(a[1]), "r"(a[2]), "r"(a[3]), "r"(b[0]), "r"(b[1]));
}

// ============ HMMA GEMM: C = A*B^T (+bias), fp16 in / fp32 acc ============
// A: [M,K] fp16 K-major; B: [N,K] fp16 K-major.
// 256 thr, 2 CTAs/SM, warp grid 2(m) x 4(n), warp tile 64x32, BK=64, 3-stage cp.async.
// remap=1 (GEMM1): n0<2048 -> Cz fp32; n0<4096 -> Cxh fp16 (col-2048);
//   tile 32 (remapped to DIP col 4224) -> Cdt fp32 pitch 32. bias indexed in DIP space.
// remap=0: single fp32 output Cz, pitch N.
__global__ void __launch_bounds__(256, 2) k_mm(
    const __half* __restrict__ Ah, const __half* __restrict__ Bh,
    const float* __restrict__ bias,
    float* __restrict__ Cz, __half* __restrict__ Cxh, float* __restrict__ Cdt,
    int M, int N, int K, int remap)
{
    extern __shared__ char smraw[];
    const uint32_t sb = (s2u(smraw) + 1023u) & ~1023u;
    const int t = threadIdx.x;
    const int wid = t >> 5, lane = t & 31;
    const int wm = wid & 1, wn = wid >> 1;       // warp tile origin (wm*64, wn*32)
    const int m0 = blockIdx.y * BM;
    int n0 = blockIdx.x * BN;
    if (remap && (int)blockIdx.x == 32) n0 = 4224;
    const int nk = K / BK;

    // per-block output routing
    float* outf = Cz; __half* outh = 0; int pitch, coff, is_half = 0;
    if (remap) {
        if (n0 < 2048)      { outf = Cz;  pitch = 2048; coff = 0; }
        else if (n0 < 4096) { outh = Cxh; pitch = 2048; coff = 2048; is_half = 1; }
        else                { outf = Cdt; pitch = 32;   coff = 4224; }
    } else { pitch = N; coff = 0; }

    auto load_tile = [&](int kt, int st) {
        const uint32_t base = sb + st * STAGE_B;
        const size_t kof = (size_t)kt * BK;
#pragma unroll
        for (int i = 0; i < 4; i++) {            // A: 128 rows x 8 chunks = 1024 slots
            int id = t + i * 256;
            int r = id >> 3, c = id & 7;
            uint32_t off = SWZ((uint32_t)(r * 128 + c * 16));
            cp16(base + off, Ah + (size_t)(m0 + r) * K + kof + c * 8);
        }
#pragma unroll
        for (int i = 0; i < 4; i++) {            // B: 128 rows x 8 chunks
            int id = t + i * 256;
            int r = id >> 3, c = id & 7;
            int gn = n0 + r; if (gn >= N) gn = N - 1;   // clamp (junk cols unstored)
            uint32_t off = SWZ((uint32_t)(r * 128 + c * 16));
            cp16(base + A_B + off, Bh + (size_t)gn * K + kof + c * 8);
        }
        asm volatile("cp.async.commit_group;" ::: "memory");
    };

    float acc[4][4][4];
#pragma unroll
    for (int i = 0; i < 4; i++)
#pragma unroll
        for (int j = 0; j < 4; j++)
#pragma unroll
            for (int v = 0; v < 4; v++) acc[i][j][v] = 0.f;

    load_tile(0, 0);
    load_tile(1, 1);

    for (int kt = 0; kt < nk; kt++) {
        asm volatile("cp.async.wait_group 1;" ::: "memory");
        __syncthreads();   // all warps done with stage (kt-1)%3 before it is overwritten below

        if (kt + 2 < nk) {
            load_tile(kt + 2, (kt + 2) % STAGES);
        } else {
            asm volatile("cp.async.commit_group;" ::: "memory");   // keep group count invariant
        }

        const int st = kt % STAGES;
        const uint32_t abase = sb + st * STAGE_B;
        const uint32_t bbase = abase + A_B;

#pragma unroll
        for (int k16 = 0; k16 < 4; k16++) {
            const int kbyte = k16 * 32;
            uint32_t af[4][4], bf[8];
#pragma unroll
            for (int mt = 0; mt < 4; mt++) {
                int r = wm * 64 + mt * 16 + (lane & 15);
                int cb = kbyte + ((lane >> 4) << 4);
                uint32_t off = SWZ((uint32_t)(r * 128 + cb));
                ldm4(af[mt], abase + off);
            }
#pragma unroll
            for (int bt = 0; bt < 2; bt++) {
                int r = wn * 32 + bt * 16 + (lane & 7) + ((lane & 16) >> 1);
                int cb = kbyte + ((lane & 8) << 1);
                uint32_t off = SWZ((uint32_t)(r * 128 + cb));
                ldm4(&bf[bt * 4], bbase + off);
            }
#pragma unroll
            for (int mt = 0; mt < 4; mt++)
#pragma unroll
                for (int nt = 0; nt < 4; nt++)
                    mma16816(acc[mt][nt], af[mt], &bf[nt * 2]);
        }
        // no trailing barrier: next iteration's top barrier protects stage reuse
    }

    // ---- epilogue: routed stores ----
    const int qr = lane >> 2;
    const int qc = (lane & 3) * 2;
#pragma unroll
    for (int mt = 0; mt < 4; mt++) {
        const int gmA = m0 + wm * 64 + mt * 16 + qr;
#pragma unroll
        for (int nt = 0; nt < 4; nt++) {
            const int gn = n0 + wn * 32 + nt * 8 + qc;     // global col (DIP space for remap)
            const int lc = gn - coff;
            if (lc < pitch) {
                float bx = 0.f, by = 0.f;
                if (bias) { bx = bias[gn]; by = bias[gn + 1]; }
                float v00 = acc[mt][nt][0] + bx, v01 = acc[mt][nt][1] + by;
                float v10 = acc[mt][nt][2] + bx, v11 = acc[mt][nt][3] + by;
                if (is_half) {
                    *(__half2*)(outh + (size_t)gmA * pitch + lc) = __floats2half2_rn(v00, v01);
                    *(__half2*)(outh + (size_t)(gmA + 8) * pitch + lc) = __floats2half2_rn(v10, v11);
                } else {
                    *(float2*)(outf + (size_t)gmA * pitch + lc) = make_float2(v00, v01);
                    *(float2*)(outf + (size_t)(gmA + 8) * pitch + lc) = make_float2(v10, v11);
                }
            }
        }
    }
}

// ---------------- fp32 -> fp16 ----------------
__global__ void k_split_h(const float* __restrict__ s, __half* __restrict__ h, size_t n)
{
    size_t i = (size_t)blockIdx.x * blockDim.x + threadIdx.x;
    if (i >= n) return;
    h[i] = __float2half_rn(s[i]);
}

// ---------------- tiny reductions ----------------
__global__ void k_reduce_bwbb(const float* __restrict__ bw, const float* __restrict__ bb) {
    __shared__ float s1[128], s2[128];
    int t = threadIdx.x;
    s1[t] = bw[t]; s2[t] = bb[t];
    __syncthreads();
    for (int o = 64; o > 0; o >>= 1) {
        if (t < o) { s1[t] += s1[t + o]; s2[t] += s2[t + o]; }
        __syncthreads();
    }
    if (t == 0) { g_scal[0] = s1[0]; g_scal[1] = s2[0]; }
}

// ---------------- e/w precompute (dense dt reads) ----------------
__global__ void k_ew(const float* __restrict__ reward,
                     const float* __restrict__ dt_bias,
                     const float* __restrict__ A_log)
{
    int idx = blockIdx.x * blockDim.x + threadIdx.x;
    if (idx >= NROWS * NH) return;
    int row = idx / NH;
    int h = idx % NH;
    float raw = g_dt[(size_t)row * 32 + h] + dt_bias[h];
    float dt = (raw > 20.f) ? raw : log1pf(expf(raw));
    float a = -expf(A_log[h]);
    float Bs = reward[row] * g_scal[0] + g_scal[1];
    g_e[idx] = expf(a * dt);
    g_w[idx] = Bs * dt;
}

// ---------------- pass A: fused conv + local scan, carries only ----------------
__global__ void __launch_bounds__(64) k_scanA(const float* __restrict__ conv_w,
                                              const float* __restrict__ conv_b)
{
    const int bid = blockIdx.x;
    const int h = bid % NH;
    const int tt = (bid / NH) % NT;
    const int b = bid / (NH * NT);
    const int p = threadIdx.x;
    const int row0 = b * LL + tt * CHUNKT;
    const int c = h * HD + p;

    __shared__ float se[CHUNKT], sw[CHUNKT];
    se[p] = g_e[(row0 + p) * NH + h];
    sw[p] = g_w[(row0 + p) * NH + h];
    __syncthreads();

    const float w0 = conv_w[c * 4 + 0], w1 = conv_w[c * 4 + 1];
    const float w2 = conv_w[c * 4 + 2], w3 = conv_w[c * 4 + 3];
    const float cb = conv_b[c];

    float x0 = 0.f, x1 = 0.f, x2 = 0.f;
    if (tt > 0) {
        x0 = __half2float(g_xh[(size_t)(row0 - 3) * DINNER + c]);
        x1 = __half2float(g_xh[(size_t)(row0 - 2) * DINNER + c]);
        x2 = __half2float(g_xh[(size_t)(row0 - 1) * DINNER + c]);
    }
    float r = 0.f;
    for (int i = 0; i < CHUNKT; i++) {
        float xn = __half2float(g_xh[(size_t)(row0 + i) * DINNER + c]);
        float a = cb + x0 * w0 + x1 * w1 + x2 * w2 + xn * w3;
        float xs = 1.f / (1.f + expf(-a)) + 0.1f * a;
        r = se[i] * r + sw[i] * xs;
        x0 = x1; x1 = x2; x2 = xn;
    }
    g_carry[bid * HD + p] = r;
    if (p == 0) {
        float E = 1.f;
        for (int i = 0; i < CHUNKT; i++) E *= se[i];
        g_Etot[bid] = E;
    }
}

// ---------------- pass B: scan carries across chunks ----------------
__global__ void k_scanB()
{
    int idx = blockIdx.x * blockDim.x + threadIdx.x;
    if (idx >= BB * NH * HD) return;
    int p = idx % HD;
    int h = (idx / HD) % NH;
    int b = idx / (HD * NH);
    float c = 0.f;
    for (int tt = 0; tt < NT; tt++) {
        int bid = (b * NT + tt) * NH + h;
        g_S[bid * HD + p] = c;
        c = g_Etot[bid] * c + g_carry[bid * HD + p];
    }
}

// ---------------- pass C: conv + scan + inter-chunk fixup + gate -> fp16 yh ----------------
__global__ void __launch_bounds__(64) k_scanC(const float* __restrict__ conv_w,
                                              const float* __restrict__ conv_b)
{
    const int bid = blockIdx.x;
    const int h = bid % NH;
    const int tt = (bid / NH) % NT;
    const int b = bid / (NH * NT);
    const int p = threadIdx.x;
    const int row0 = b * LL + tt * CHUNKT;
    const int c = h * HD + p;

    __shared__ float se[CHUNKT], sw[CHUNKT], sp[CHUNKT];
    se[p] = g_e[(row0 + p) * NH + h];
    sw[p] = g_w[(row0 + p) * NH + h];
    __syncthreads();
    if (p == 0) {
        float r = 1.f;
        for (int i = 0; i < CHUNKT; i++) { r *= se[i]; sp[i] = r; }
    }
    __syncthreads();

    const float w0 = conv_w[c * 4 + 0], w1 = conv_w[c * 4 + 1];
    const float w2 = conv_w[c * 4 + 2], w3 = conv_w[c * 4 + 3];
    const float cb = conv_b[c];
    const float Sv = g_S[bid * HD + p];

    float x0 = 0.f, x1 = 0.f, x2 = 0.f;
    if (tt > 0) {
        x0 = __half2float(g_xh[(size_t)(row0 - 3) * DINNER + c]);
        x1 = __half2float(g_xh[(size_t)(row0 - 2) * DINNER + c]);
        x2 = __half2float(g_xh[(size_t)(row0 - 1) * DINNER + c]);
    }
    float r = 0.f;
    for (int i = 0; i < CHUNKT; i++) {
        const size_t rowi = (size_t)(row0 + i);
        float xn = __half2float(g_xh[rowi * DINNER + c]);
        float a = cb + x0 * w0 + x1 * w1 + x2 * w2 + xn * w3;
        float xs = 1.f / (1.f + expf(-a)) + 0.1f * a;
        r = se[i] * r + sw[i] * xs;
        x0 = x1; x1 = x2; x2 = xn;
        float y = r + Sv * sp[i];
        float z = g_z[rowi * DINNER + c];
        float g = y * (1.f / (1.f + expf(-z)) + 0.1f * z);
        g_yh[rowi * DINNER + c] = __float2half_rn(g);
    }
}

// ---------------- launch ----------------
extern "C" void kernel_launch(void* const* d_in, const int* in_sizes, int n_in,
                              void* d_out, int out_size)
{
    const float* u       = (const float*)d_in[0];
    const float* reward  = (const float*)d_in[1];
    const float* in_w    = (const float*)d_in[2];
    const float* in_b    = (const float*)d_in[3];
    const float* conv_w  = (const float*)d_in[4];
    const float* conv_b  = (const float*)d_in[5];
    const float* bw      = (const float*)d_in[6];
    const float* bb      = (const float*)d_in[7];
    const float* dt_bias = (const float*)d_in[8];
    const float* A_log   = (const float*)d_in[9];
    const float* out_w   = (const float*)d_in[10];
    float* out = (float*)d_out;

    cudaFuncSetAttribute(k_mm, cudaFuncAttributeMaxDynamicSharedMemorySize, SMEM_DYN);

    float *zp, *dtp;
    __half *xhp, *uh, *w1h, *yh, *w2h;
    cudaGetSymbolAddress((void**)&zp, g_z);
    cudaGetSymbolAddress((void**)&xhp, g_xh);
    cudaGetSymbolAddress((void**)&dtp, g_dt);
    cudaGetSymbolAddress((void**)&uh, g_uh);
    cudaGetSymbolAddress((void**)&w1h, g_w1h);
    cudaGetSymbolAddress((void**)&yh, g_yh);
    cudaGetSymbolAddress((void**)&w2h, g_w2h);

    // conversions
    {
        size_t n = (size_t)NROWS * DMODEL;
        k_split_h<<<(unsigned)((n + 255) / 256), 256>>>(u, uh, n);
    }
    {
        size_t n = (size_t)DIP * DMODEL;
        k_split_h<<<(unsigned)((n + 255) / 256), 256>>>(in_w, w1h, n);
    }
    {
        size_t n = (size_t)DMODEL * DINNER;
        k_split_h<<<(unsigned)((n + 255) / 256), 256>>>(out_w, w2h, n);
    }

    // GEMM1: routed outputs z(fp32)/x(fp16)/dt(fp32)  (M=16384, K=1024)
    {
        dim3 grid(33, NROWS / BM);
        k_mm<<<grid, 256, SMEM_DYN>>>(uh, w1h, in_b, zp, xhp, dtp, NROWS, DIP, DMODEL, 1);
    }

    k_reduce_bwbb<<<1, 128>>>(bw, bb);
    {
        int n = NROWS * NH;
        k_ew<<<(n + 255) / 256, 256>>>(reward, dt_bias, A_log);
    }
    k_scanA<<<BB * NT * NH, 64>>>(conv_w, conv_b);
    {
        int n = BB * NH * HD;
        k_scanB<<<(n + 255) / 256, 256>>>();
    }
    k_scanC<<<BB * NT * NH, 64>>>(conv_w, conv_b);

    // GEMM2: out[16384, 1024] = y_gated @ out_w^T  (K=2048)
    {
        dim3 grid(DMODEL / BN, NROWS / BM);
        k_mm<<<grid, 256, SMEM_DYN>>>(yh, w2h, nullptr, out, nullptr, nullptr, NROWS, DMODEL, DINNER, 0);
    }
}

// round 16
// speedup vs baseline: 1.6210x; 1.0682x over previous
#include <cuda_runtime.h>
#include <cuda_fp16.h>
#include <math.h>
#include <stdint.h>

// ---------------- problem constants ----------------
#define BB      4
#define LL      4096
#define DMODEL  1024
#define DINNER  2048
#define NH      32
#define HD      64
#define DIP     4256
#define NROWS   (BB*LL)
#define CHUNKT  64
#define NT      (LL/CHUNKT)

// ---------------- GEMM tiling ----------------
#define BM 128
#define BN 128
#define BK 64                     // fp16 K elems per stage (128 bytes per row)
#define STAGES 3
#define A_B     16384             // 128 rows x 128 bytes
#define B_B     16384
#define STAGE_B (A_B + B_B)       // 32 KB
#define SMEM_DYN (STAGES*STAGE_B + 1024)

// ---------------- scratch ----------------
__device__ __half g_zh[(size_t)NROWS * DINNER];   // gate pre-activation (fp16)
__device__ __half g_xh[(size_t)NROWS * DINNER];   // conv input (fp16)
__device__ float  g_dt[(size_t)NROWS * 32];       // dt raw
__device__ float  g_carry[BB * NT * NH * HD];
__device__ float  g_Etot[BB * NT * NH];
__device__ float  g_S[BB * NT * NH * HD];
__device__ float  g_scal[2];
__device__ __half g_uh[(size_t)NROWS * DMODEL];
__device__ __half g_w1h[(size_t)DIP * DMODEL];
__device__ __half g_yh[(size_t)NROWS * DINNER];
__device__ __half g_w2h[(size_t)DMODEL * DINNER];

// ---------------- helpers ----------------
__device__ __forceinline__ uint32_t s2u(const void* p) {
    uint32_t a;
    asm("{ .reg .u64 t; cvta.to.shared.u64 t, %1; cvt.u32.u64 %0, t; }" : "=r"(a) : "l"(p));
    return a;
}
#define SWZ(x) ((x) ^ (((x) >> 3) & 0x70))

__device__ __forceinline__ void cp16(uint32_t dst, const void* src) {
    asm volatile("cp.async.cg.shared.global [%0], [%1], 16;"
                 :: "r"(dst), "l"(src) : "memory");
}
__device__ __forceinline__ void ldm4(uint32_t* r, uint32_t addr) {
    asm volatile("ldmatrix.sync.aligned.m8n8.x4.shared.b16 {%0,%1,%2,%3}, [%4];"
                 : "=r"(r[0]), "=r"(r[1]), "=r"(r[2]), "=r"(r[3]) : "r"(addr));
}
__device__ __forceinline__ void mma16816(float* d, const uint32_t* a, const uint32_t* b) {
    asm volatile(
        "mma.sync.aligned.m16n8k16.row.col.f32.f16.f16.f32 "
        "{%0,%1,%2,%3}, {%4,%5,%6,%7}, {%8,%9}, {%0,%1,%2,%3};"
        : "+f"(d[0]), "+f"(d[1]), "+f"(d[2]), "+f"(d[3])
        : "r"(a[0]), "r"(a[1]), "r"(a[2]), "r"(a[3]), "r"(b[0]), "r"(b[1]));
}

// ============ HMMA GEMM: C = A*B^T (+bias), fp16 in / fp32 acc ============
// A: [M,K] fp16 K-major; B: [N,K] fp16 K-major.
// 128 thr, 2 CTAs/SM, warp grid 2(m) x 2(n), warp tile 64x64, BK=64, 3-stage cp.async.
// remap=1 (GEMM1): n0<2048 -> Czh fp16; n0<4096 -> Cxh fp16 (col-2048);
//   tile 32 (remapped to DIP col 4224) -> Cdt fp32 pitch 32. bias indexed in DIP space.
// remap=0: single fp32 output Cf, pitch N.
__global__ void __launch_bounds__(128, 2) k_mm(
    const __half* __restrict__ Ah, const __half* __restrict__ Bh,
    const float* __restrict__ bias,
    __half* __restrict__ Czh, __half* __restrict__ Cxh,
    float* __restrict__ Cdt, float* __restrict__ Cf,
    int M, int N, int K, int remap)
{
    extern __shared__ char smraw[];
    const uint32_t sb = (s2u(smraw) + 1023u) & ~1023u;
    const int t = threadIdx.x;
    const int wid = t >> 5, lane = t & 31;
    const int wm = wid & 1, wn = wid >> 1;       // warp tile origin (wm*64, wn*64)
    const int m0 = blockIdx.y * BM;
    int n0 = blockIdx.x * BN;
    if (remap && (int)blockIdx.x == 32) n0 = 4224;
    const int nk = K / BK;

    // per-block output routing
    __half* outh = 0; float* outf = 0; int pitch, coff, is_half = 0;
    if (remap) {
        if (n0 < 2048)      { outh = Czh; pitch = 2048; coff = 0;    is_half = 1; }
        else if (n0 < 4096) { outh = Cxh; pitch = 2048; coff = 2048; is_half = 1; }
        else                { outf = Cdt; pitch = 32;   coff = 4224; }
    } else { outf = Cf; pitch = N; coff = 0; }

    auto load_tile = [&](int kt, int st) {
        const uint32_t base = sb + st * STAGE_B;
        const size_t kof = (size_t)kt * BK;
#pragma unroll
        for (int i = 0; i < 8; i++) {            // A: 128 rows x 8 chunks = 1024 slots
            int id = t + i * 128;
            int r = id >> 3, c = id & 7;
            uint32_t off = SWZ((uint32_t)(r * 128 + c * 16));
            cp16(base + off, Ah + (size_t)(m0 + r) * K + kof + c * 8);
        }
#pragma unroll
        for (int i = 0; i < 8; i++) {            // B: 128 rows x 8 chunks
            int id = t + i * 128;
            int r = id >> 3, c = id & 7;
            int gn = n0 + r; if (gn >= N) gn = N - 1;   // clamp (junk cols unstored)
            uint32_t off = SWZ((uint32_t)(r * 128 + c * 16));
            cp16(base + A_B + off, Bh + (size_t)gn * K + kof + c * 8);
        }
        asm volatile("cp.async.commit_group;" ::: "memory");
    };

    float acc[4][8][4];
#pragma unroll
    for (int i = 0; i < 4; i++)
#pragma unroll
        for (int j = 0; j < 8; j++)
#pragma unroll
            for (int v = 0; v < 4; v++) acc[i][j][v] = 0.f;

    load_tile(0, 0);
    load_tile(1, 1);

    for (int kt = 0; kt < nk; kt++) {
        asm volatile("cp.async.wait_group 1;" ::: "memory");
        __syncthreads();   // all warps done with stage (kt-1)%3 before it is overwritten below

        if (kt + 2 < nk) {
            load_tile(kt + 2, (kt + 2) % STAGES);
        } else {
            asm volatile("cp.async.commit_group;" ::: "memory");   // keep group count invariant
        }

        const int st = kt % STAGES;
        const uint32_t abase = sb + st * STAGE_B;
        const uint32_t bbase = abase + A_B;

#pragma unroll
        for (int k16 = 0; k16 < 4; k16++) {
            const int kbyte = k16 * 32;
            uint32_t af[4][4], bf[16];
#pragma unroll
            for (int mt = 0; mt < 4; mt++) {
                int r = wm * 64 + mt * 16 + (lane & 15);
                int cb = kbyte + ((lane >> 4) << 4);
                uint32_t off = SWZ((uint32_t)(r * 128 + cb));
                ldm4(af[mt], abase + off);
            }
#pragma unroll
            for (int bt = 0; bt < 4; bt++) {
                int r = wn * 64 + bt * 16 + (lane & 7) + ((lane & 16) >> 1);
                int cb = kbyte + ((lane & 8) << 1);
                uint32_t off = SWZ((uint32_t)(r * 128 + cb));
                ldm4(&bf[bt * 4], bbase + off);
            }
#pragma unroll
            for (int mt = 0; mt < 4; mt++)
#pragma unroll
                for (int nt = 0; nt < 8; nt++)
                    mma16816(acc[mt][nt], af[mt], &bf[nt * 2]);
        }
        // no trailing barrier: next iteration's top barrier protects stage reuse
    }

    // ---- epilogue: routed stores ----
    const int qr = lane >> 2;
    const int qc = (lane & 3) * 2;
#pragma unroll
    for (int mt = 0; mt < 4; mt++) {
        const int gmA = m0 + wm * 64 + mt * 16 + qr;
#pragma unroll
        for (int nt = 0; nt < 8; nt++) {
            const int gn = n0 + wn * 64 + nt * 8 + qc;     // global col (DIP space for remap)
            const int lc = gn - coff;
            if (lc < pitch) {
                float bx = 0.f, by = 0.f;
                if (bias) { bx = bias[gn]; by = bias[gn + 1]; }
                float v00 = acc[mt][nt][0] + bx, v01 = acc[mt][nt][1] + by;
                float v10 = acc[mt][nt][2] + bx, v11 = acc[mt][nt][3] + by;
                if (is_half) {
                    *(__half2*)(outh + (size_t)gmA * pitch + lc) = __floats2half2_rn(v00, v01);
                    *(__half2*)(outh + (size_t)(gmA + 8) * pitch + lc) = __floats2half2_rn(v10, v11);
                } else {
                    *(float2*)(outf + (size_t)gmA * pitch + lc) = make_float2(v00, v01);
                    *(float2*)(outf + (size_t)(gmA + 8) * pitch + lc) = make_float2(v10, v11);
                }
            }
        }
    }
}

// ---------------- fp32 -> fp16 ----------------
__global__ void k_split_h(const float* __restrict__ s, __half* __restrict__ h, size_t n)
{
    size_t i = (size_t)blockIdx.x * blockDim.x + threadIdx.x;
    if (i >= n) return;
    h[i] = __float2half_rn(s[i]);
}

// ---------------- tiny reductions ----------------
__global__ void k_reduce_bwbb(const float* __restrict__ bw, const float* __restrict__ bb) {
    __shared__ float s1[128], s2[128];
    int t = threadIdx.x;
    s1[t] = bw[t]; s2[t] = bb[t];
    __syncthreads();
    for (int o = 64; o > 0; o >>= 1) {
        if (t < o) { s1[t] += s1[t + o]; s2[t] += s2[t + o]; }
        __syncthreads();
    }
    if (t == 0) { g_scal[0] = s1[0]; g_scal[1] = s2[0]; }
}

// e/w computation inlined into scan kernels:
//   raw = dt[row][h] + dt_bias[h]; dt = softplus(raw)
//   e = exp(-exp(A_log[h]) * dt); w = (reward[row]*sum_bw + sum_bb) * dt

// ---------------- pass A: fused e/w + conv + local scan, carries only ----------------
__global__ void __launch_bounds__(64) k_scanA(const float* __restrict__ conv_w,
                                              const float* __restrict__ conv_b,
                                              const float* __restrict__ reward,
                                              const float* __restrict__ dt_bias,
                                              const float* __restrict__ A_log)
{
    const int bid = blockIdx.x;
    const int h = bid % NH;
    const int tt = (bid / NH) % NT;
    const int b = bid / (NH * NT);
    const int p = threadIdx.x;
    const int row0 = b * LL + tt * CHUNKT;
    const int c = h * HD + p;

    __shared__ float se[CHUNKT], sw[CHUNKT];
    {
        const int row = row0 + p;
        float raw = g_dt[(size_t)row * 32 + h] + dt_bias[h];
        float dtv = (raw > 20.f) ? raw : log1pf(expf(raw));
        float a = -expf(A_log[h]);
        se[p] = expf(a * dtv);
        sw[p] = (reward[row] * g_scal[0] + g_scal[1]) * dtv;
    }
    __syncthreads();

    const float w0 = conv_w[c * 4 + 0], w1 = conv_w[c * 4 + 1];
    const float w2 = conv_w[c * 4 + 2], w3 = conv_w[c * 4 + 3];
    const float cb = conv_b[c];

    float x0 = 0.f, x1 = 0.f, x2 = 0.f;
    if (tt > 0) {
        x0 = __half2float(g_xh[(size_t)(row0 - 3) * DINNER + c]);
        x1 = __half2float(g_xh[(size_t)(row0 - 2) * DINNER + c]);
        x2 = __half2float(g_xh[(size_t)(row0 - 1) * DINNER + c]);
    }
    float r = 0.f;
    for (int i = 0; i < CHUNKT; i++) {
        float xn = __half2float(g_xh[(size_t)(row0 + i) * DINNER + c]);
        float a = cb + x0 * w0 + x1 * w1 + x2 * w2 + xn * w3;
        float xs = 1.f / (1.f + expf(-a)) + 0.1f * a;
        r = se[i] * r + sw[i] * xs;
        x0 = x1; x1 = x2; x2 = xn;
    }
    g_carry[bid * HD + p] = r;
    if (p == 0) {
        float E = 1.f;
        for (int i = 0; i < CHUNKT; i++) E *= se[i];
        g_Etot[bid] = E;
    }
}

// ---------------- pass B: scan carries across chunks ----------------
__global__ void k_scanB()
{
    int idx = blockIdx.x * blockDim.x + threadIdx.x;
    if (idx >= BB * NH * HD) return;
    int p = idx % HD;
    int h = (idx / HD) % NH;
    int b = idx / (HD * NH);
    float c = 0.f;
    for (int tt = 0; tt < NT; tt++) {
        int bid = (b * NT + tt) * NH + h;
        g_S[bid * HD + p] = c;
        c = g_Etot[bid] * c + g_carry[bid * HD + p];
    }
}

// ---------------- pass C: e/w + conv + scan + fixup + gate -> fp16 yh ----------------
__global__ void __launch_bounds__(64) k_scanC(const float* __restrict__ conv_w,
                                              const float* __restrict__ conv_b,
                                              const float* __restrict__ reward,
                                              const float* __restrict__ dt_bias,
                                              const float* __restrict__ A_log)
{
    const int bid = blockIdx.x;
    const int h = bid % NH;
    const int tt = (bid / NH) % NT;
    const int b = bid / (NH * NT);
    const int p = threadIdx.x;
    const int row0 = b * LL + tt * CHUNKT;
    const int c = h * HD + p;

    __shared__ float se[CHUNKT], sw[CHUNKT], sp[CHUNKT];
    {
        const int row = row0 + p;
        float raw = g_dt[(size_t)row * 32 + h] + dt_bias[h];
        float dtv = (raw > 20.f) ? raw : log1pf(expf(raw));
        float a = -expf(A_log[h]);
        se[p] = expf(a * dtv);
        sw[p] = (reward[row] * g_scal[0] + g_scal[1]) * dtv;
    }
    __syncthreads();
    if (p == 0) {
        float r = 1.f;
        for (int i = 0; i < CHUNKT; i++) { r *= se[i]; sp[i] = r; }
    }
    __syncthreads();

    const float w0 = conv_w[c * 4 + 0], w1 = conv_w[c * 4 + 1];
    const float w2 = conv_w[c * 4 + 2], w3 = conv_w[c * 4 + 3];
    const float cb = conv_b[c];
    const float Sv = g_S[bid * HD + p];

    float x0 = 0.f, x1 = 0.f, x2 = 0.f;
    if (tt > 0) {
        x0 = __half2float(g_xh[(size_t)(row0 - 3) * DINNER + c]);
        x1 = __half2float(g_xh[(size_t)(row0 - 2) * DINNER + c]);
        x2 = __half2float(g_xh[(size_t)(row0 - 1) * DINNER + c]);
    }
    float r = 0.f;
    for (int i = 0; i < CHUNKT; i++) {
        const size_t rowi = (size_t)(row0 + i);
        float xn = __half2float(g_xh[rowi * DINNER + c]);
        float a = cb + x0 * w0 + x1 * w1 + x2 * w2 + xn * w3;
        float xs = 1.f / (1.f + expf(-a)) + 0.1f * a;
        r = se[i] * r + sw[i] * xs;
        x0 = x1; x1 = x2; x2 = xn;
        float y = r + Sv * sp[i];
        float z = __half2float(g_zh[rowi * DINNER + c]);
        float g = y * (1.f / (1.f + expf(-z)) + 0.1f * z);
        g_yh[rowi * DINNER + c] = __float2half_rn(g);
    }
}

// ---------------- launch ----------------
extern "C" void kernel_launch(void* const* d_in, const int* in_sizes, int n_in,
                              void* d_out, int out_size)
{
    const float* u       = (const float*)d_in[0];
    const float* reward  = (const float*)d_in[1];
    const float* in_w    = (const float*)d_in[2];
    const float* in_b    = (const float*)d_in[3];
    const float* conv_w  = (const float*)d_in[4];
    const float* conv_b  = (const float*)d_in[5];
    const float* bw      = (const float*)d_in[6];
    const float* bb      = (const float*)d_in[7];
    const float* dt_bias = (const float*)d_in[8];
    const float* A_log   = (const float*)d_in[9];
    const float* out_w   = (const float*)d_in[10];
    float* out = (float*)d_out;

    cudaFuncSetAttribute(k_mm, cudaFuncAttributeMaxDynamicSharedMemorySize, SMEM_DYN);

    float *dtp;
    __half *zhp, *xhp, *uh, *w1h, *yh, *w2h;
    cudaGetSymbolAddress((void**)&zhp, g_zh);
    cudaGetSymbolAddress((void**)&xhp, g_xh);
    cudaGetSymbolAddress((void**)&dtp, g_dt);
    cudaGetSymbolAddress((void**)&uh, g_uh);
    cudaGetSymbolAddress((void**)&w1h, g_w1h);
    cudaGetSymbolAddress((void**)&yh, g_yh);
    cudaGetSymbolAddress((void**)&w2h, g_w2h);

    // conversions
    {
        size_t n = (size_t)NROWS * DMODEL;
        k_split_h<<<(unsigned)((n + 255) / 256), 256>>>(u, uh, n);
    }
    {
        size_t n = (size_t)DIP * DMODEL;
        k_split_h<<<(unsigned)((n + 255) / 256), 256>>>(in_w, w1h, n);
    }
    {
        size_t n = (size_t)DMODEL * DINNER;
        k_split_h<<<(unsigned)((n + 255) / 256), 256>>>(out_w, w2h, n);
    }

    // GEMM1: routed outputs z(fp16)/x(fp16)/dt(fp32)  (M=16384, K=1024)
    {
        dim3 grid(33, NROWS / BM);
        k_mm<<<grid, 128, SMEM_DYN>>>(uh, w1h, in_b, zhp, xhp, dtp, nullptr,
                                      NROWS, DIP, DMODEL, 1);
    }

    k_reduce_bwbb<<<1, 128>>>(bw, bb);
    k_scanA<<<BB * NT * NH, 64>>>(conv_w, conv_b, reward, dt_bias, A_log);
    {
        int n = BB * NH * HD;
        k_scanB<<<(n + 255) / 256, 256>>>();
    }
    k_scanC<<<BB * NT * NH, 64>>>(conv_w, conv_b, reward, dt_bias, A_log);

    // GEMM2: out[16384, 1024] = y_gated @ out_w^T  (K=2048)
    {
        dim3 grid(DMODEL / BN, NROWS / BM);
        k_mm<<<grid, 128, SMEM_DYN>>>(yh, w2h, nullptr, nullptr, nullptr, nullptr, out,
                                      NROWS, DMODEL, DINNER, 0);
    }
}

// round 17
// speedup vs baseline: 1.6280x; 1.0043x over previous
#include <cuda_runtime.h>
#include <cuda_fp16.h>
#include <math.h>
#include <stdint.h>

// ---------------- problem constants ----------------
#define BB      4
#define LL      4096
#define DMODEL  1024
#define DINNER  2048
#define NH      32
#define HD      64
#define DIP     4256
#define NROWS   (BB*LL)
#define CHUNKT  64
#define NT      (LL/CHUNKT)

// ---------------- GEMM tiling ----------------
#define BM 128
#define BN 128
#define BK 64                     // fp16 K elems per stage (128 bytes per row)
#define STAGES 3
#define A_B     16384             // 128 rows x 128 bytes
#define B_B     16384
#define STAGE_B (A_B + B_B)       // 32 KB
#define SMEM_DYN (STAGES*STAGE_B + 1024)

// ---------------- scratch ----------------
__device__ __half g_zh[(size_t)NROWS * DINNER];   // gate pre-activation (fp16)
__device__ __half g_xh[(size_t)NROWS * DINNER];   // conv input (fp16)
__device__ float  g_dt[(size_t)NROWS * 32];       // dt raw
__device__ float  g_carry[BB * NT * NH * HD];
__device__ float  g_Etot[BB * NT * NH];
__device__ float  g_S[BB * NT * NH * HD];
__device__ float  g_scal[2];
__device__ __half g_uh[(size_t)NROWS * DMODEL];
__device__ __half g_w1h[(size_t)DIP * DMODEL];
__device__ __half g_yh[(size_t)NROWS * DINNER];
__device__ __half g_w2h[(size_t)DMODEL * DINNER];

// ---------------- helpers ----------------
__device__ __forceinline__ uint32_t s2u(const void* p) {
    uint32_t a;
    asm("{ .reg .u64 t; cvta.to.shared.u64 t, %1; cvt.u32.u64 %0, t; }" : "=r"(a) : "l"(p));
    return a;
}
#define SWZ(x) ((x) ^ (((x) >> 3) & 0x70))

__device__ __forceinline__ void cp16(uint32_t dst, const void* src) {
    asm volatile("cp.async.cg.shared.global [%0], [%1], 16;"
                 :: "r"(dst), "l"(src) : "memory");
}
__device__ __forceinline__ void ldm4(uint32_t* r, uint32_t addr) {
    asm volatile("ldmatrix.sync.aligned.m8n8.x4.shared.b16 {%0,%1,%2,%3}, [%4];"
                 : "=r"(r[0]), "=r"(r[1]), "=r"(r[2]), "=r"(r[3]) : "r"(addr));
}
__device__ __forceinline__ void mma16816(float* d, const uint32_t* a, const uint32_t* b) {
    asm volatile(
        "mma.sync.aligned.m16n8k16.row.col.f32.f16.f16.f32 "
        "{%0,%1,%2,%3}, {%4,%5,%6,%7}, {%8,%9}, {%0,%1,%2,%3};"
        : "+f"(d[0]), "+f"(d[1]), "+f"(d[2]), "+f"(d[3])
        : "r"(a[0]), "r"(a[1]), "r"(a[2]), "r"(a[3]), "r"(b[0]), "r"(b[1]));
}
__device__ __forceinline__ float fsig(float a) {           // silu' = sigmoid(a) + 0.1a
    return __frcp_rn(1.f + __expf(-a)) + 0.1f * a;
}

// ============ HMMA GEMM: C = A*B^T (+bias), fp16 in / fp32 acc ============
// 128 thr, 2 CTAs/SM, warp grid 2(m) x 2(n), warp tile 64x64, BK=64, 3-stage cp.async,
// fragment double-buffering across the k16 loop.
// remap=1 (GEMM1): n0<2048 -> Czh fp16; n0<4096 -> Cxh fp16 (col-2048);
//   tile 32 (remapped to DIP col 4224) -> Cdt fp32 pitch 32. bias indexed in DIP space.
// remap=0: single fp32 output Cf, pitch N.
__global__ void __launch_bounds__(128, 2) k_mm(
    const __half* __restrict__ Ah, const __half* __restrict__ Bh,
    const float* __restrict__ bias,
    __half* __restrict__ Czh, __half* __restrict__ Cxh,
    float* __restrict__ Cdt, float* __restrict__ Cf,
    int M, int N, int K, int remap)
{
    extern __shared__ char smraw[];
    const uint32_t sb = (s2u(smraw) + 1023u) & ~1023u;
    const int t = threadIdx.x;
    const int wid = t >> 5, lane = t & 31;
    const int wm = wid & 1, wn = wid >> 1;       // warp tile origin (wm*64, wn*64)
    const int m0 = blockIdx.y * BM;
    int n0 = blockIdx.x * BN;
    if (remap && (int)blockIdx.x == 32) n0 = 4224;
    const int nk = K / BK;

    // per-block output routing
    __half* outh = 0; float* outf = 0; int pitch, coff, is_half = 0;
    if (remap) {
        if (n0 < 2048)      { outh = Czh; pitch = 2048; coff = 0;    is_half = 1; }
        else if (n0 < 4096) { outh = Cxh; pitch = 2048; coff = 2048; is_half = 1; }
        else                { outf = Cdt; pitch = 32;   coff = 4224; }
    } else { outf = Cf; pitch = N; coff = 0; }

    auto load_tile = [&](int kt, int st) {
        const uint32_t base = sb + st * STAGE_B;
        const size_t kof = (size_t)kt * BK;
#pragma unroll
        for (int i = 0; i < 8; i++) {            // A: 128 rows x 8 chunks
            int id = t + i * 128;
            int r = id >> 3, c = id & 7;
            uint32_t off = SWZ((uint32_t)(r * 128 + c * 16));
            cp16(base + off, Ah + (size_t)(m0 + r) * K + kof + c * 8);
        }
#pragma unroll
        for (int i = 0; i < 8; i++) {            // B: 128 rows x 8 chunks
            int id = t + i * 128;
            int r = id >> 3, c = id & 7;
            int gn = n0 + r; if (gn >= N) gn = N - 1;   // clamp (junk cols unstored)
            uint32_t off = SWZ((uint32_t)(r * 128 + c * 16));
            cp16(base + A_B + off, Bh + (size_t)gn * K + kof + c * 8);
        }
        asm volatile("cp.async.commit_group;" ::: "memory");
    };

    // fragment loader for one k16 step from stage bases
    const int ar_ = (lane & 15);
    const int ac_ = ((lane >> 4) << 4);
    const int br_ = (lane & 7) + ((lane & 16) >> 1);
    const int bc_ = ((lane & 8) << 1);
    auto load_frags = [&](uint32_t abase, uint32_t bbase, int k16,
                          uint32_t af[4][4], uint32_t bf[16]) {
        const int kbyte = k16 * 32;
#pragma unroll
        for (int mt = 0; mt < 4; mt++) {
            int r = wm * 64 + mt * 16 + ar_;
            uint32_t off = SWZ((uint32_t)(r * 128 + kbyte + ac_));
            ldm4(af[mt], abase + off);
        }
#pragma unroll
        for (int bt = 0; bt < 4; bt++) {
            int r = wn * 64 + bt * 16 + br_;
            uint32_t off = SWZ((uint32_t)(r * 128 + kbyte + bc_));
            ldm4(&bf[bt * 4], bbase + off);
        }
    };

    float acc[4][8][4];
#pragma unroll
    for (int i = 0; i < 4; i++)
#pragma unroll
        for (int j = 0; j < 8; j++)
#pragma unroll
            for (int v = 0; v < 4; v++) acc[i][j][v] = 0.f;

    load_tile(0, 0);
    load_tile(1, 1);

    uint32_t afb[2][4][4], bfb[2][16];

    for (int kt = 0; kt < nk; kt++) {
        asm volatile("cp.async.wait_group 1;" ::: "memory");
        __syncthreads();   // all warps done with stage (kt-1)%3 before it is overwritten below

        if (kt + 2 < nk) {
            load_tile(kt + 2, (kt + 2) % STAGES);
        } else {
            asm volatile("cp.async.commit_group;" ::: "memory");   // keep group count invariant
        }

        const int st = kt % STAGES;
        const uint32_t abase = sb + st * STAGE_B;
        const uint32_t bbase = abase + A_B;

        load_frags(abase, bbase, 0, afb[0], bfb[0]);
#pragma unroll
        for (int k16 = 0; k16 < 4; k16++) {
            const int cur = k16 & 1;
            if (k16 < 3)
                load_frags(abase, bbase, k16 + 1, afb[cur ^ 1], bfb[cur ^ 1]);
#pragma unroll
            for (int mt = 0; mt < 4; mt++)
#pragma unroll
                for (int nt = 0; nt < 8; nt++)
                    mma16816(acc[mt][nt], afb[cur][mt], &bfb[cur][nt * 2]);
        }
        // no trailing barrier: next iteration's top barrier protects stage reuse
    }

    // ---- epilogue: routed stores ----
    const int qr = lane >> 2;
    const int qc = (lane & 3) * 2;
#pragma unroll
    for (int mt = 0; mt < 4; mt++) {
        const int gmA = m0 + wm * 64 + mt * 16 + qr;
#pragma unroll
        for (int nt = 0; nt < 8; nt++) {
            const int gn = n0 + wn * 64 + nt * 8 + qc;     // global col (DIP space for remap)
            const int lc = gn - coff;
            if (lc < pitch) {
                float bx = 0.f, by = 0.f;
                if (bias) { bx = bias[gn]; by = bias[gn + 1]; }
                float v00 = acc[mt][nt][0] + bx, v01 = acc[mt][nt][1] + by;
                float v10 = acc[mt][nt][2] + bx, v11 = acc[mt][nt][3] + by;
                if (is_half) {
                    *(__half2*)(outh + (size_t)gmA * pitch + lc) = __floats2half2_rn(v00, v01);
                    *(__half2*)(outh + (size_t)(gmA + 8) * pitch + lc) = __floats2half2_rn(v10, v11);
                } else {
                    *(float2*)(outf + (size_t)gmA * pitch + lc) = make_float2(v00, v01);
                    *(float2*)(outf + (size_t)(gmA + 8) * pitch + lc) = make_float2(v10, v11);
                }
            }
        }
    }
}

// ---------------- fused fp32 -> fp16 conversion of u, in_w, out_w ----------------
#define N_U   ((size_t)NROWS * DMODEL)
#define N_W1  ((size_t)DIP * DMODEL)
#define N_W2  ((size_t)DMODEL * DINNER)
__global__ void k_convert(const float* __restrict__ u, const float* __restrict__ w1,
                          const float* __restrict__ w2)
{
    size_t i = (size_t)blockIdx.x * blockDim.x + threadIdx.x;
    if (i < N_U) {
        g_uh[i] = __float2half_rn(u[i]);
    } else if (i < N_U + N_W1) {
        size_t j = i - N_U;
        g_w1h[j] = __float2half_rn(w1[j]);
    } else if (i < N_U + N_W1 + N_W2) {
        size_t j = i - N_U - N_W1;
        g_w2h[j] = __float2half_rn(w2[j]);
    }
}

// ---------------- tiny reductions ----------------
__global__ void k_reduce_bwbb(const float* __restrict__ bw, const float* __restrict__ bb) {
    __shared__ float s1[128], s2[128];
    int t = threadIdx.x;
    s1[t] = bw[t]; s2[t] = bb[t];
    __syncthreads();
    for (int o = 64; o > 0; o >>= 1) {
        if (t < o) { s1[t] += s1[t + o]; s2[t] += s2[t + o]; }
        __syncthreads();
    }
    if (t == 0) { g_scal[0] = s1[0]; g_scal[1] = s2[0]; }
}

// ---------------- pass A: fused e/w + conv + local scan, carries only ----------------
__global__ void __launch_bounds__(64) k_scanA(const float* __restrict__ conv_w,
                                              const float* __restrict__ conv_b,
                                              const float* __restrict__ reward,
                                              const float* __restrict__ dt_bias,
                                              const float* __restrict__ A_log)
{
    const int bid = blockIdx.x;
    const int h = bid % NH;
    const int tt = (bid / NH) % NT;
    const int b = bid / (NH * NT);
    const int p = threadIdx.x;
    const int row0 = b * LL + tt * CHUNKT;
    const int c = h * HD + p;

    __shared__ float se[CHUNKT], sw[CHUNKT];
    {
        const int row = row0 + p;
        float raw = g_dt[(size_t)row * 32 + h] + dt_bias[h];
        float dtv = (raw > 20.f) ? raw : log1pf(__expf(raw));
        float a = -__expf(A_log[h]);
        se[p] = __expf(a * dtv);
        sw[p] = (reward[row] * g_scal[0] + g_scal[1]) * dtv;
    }
    __syncthreads();

    const float w0 = conv_w[c * 4 + 0], w1 = conv_w[c * 4 + 1];
    const float w2 = conv_w[c * 4 + 2], w3 = conv_w[c * 4 + 3];
    const float cb = conv_b[c];

    float x0 = 0.f, x1 = 0.f, x2 = 0.f;
    if (tt > 0) {
        x0 = __half2float(g_xh[(size_t)(row0 - 3) * DINNER + c]);
        x1 = __half2float(g_xh[(size_t)(row0 - 2) * DINNER + c]);
        x2 = __half2float(g_xh[(size_t)(row0 - 1) * DINNER + c]);
    }
    float r = 0.f;
    for (int i = 0; i < CHUNKT; i++) {
        float xn = __half2float(g_xh[(size_t)(row0 + i) * DINNER + c]);
        float a = cb + x0 * w0 + x1 * w1 + x2 * w2 + xn * w3;
        r = se[i] * r + sw[i] * fsig(a);
        x0 = x1; x1 = x2; x2 = xn;
    }
    g_carry[bid * HD + p] = r;
    if (p == 0) {
        float E = 1.f;
        for (int i = 0; i < CHUNKT; i++) E *= se[i];
        g_Etot[bid] = E;
    }
}

// ---------------- pass B: scan carries across chunks ----------------
__global__ void k_scanB()
{
    int idx = blockIdx.x * blockDim.x + threadIdx.x;
    if (idx >= BB * NH * HD) return;
    int p = idx % HD;
    int h = (idx / HD) % NH;
    int b = idx / (HD * NH);
    float c = 0.f;
    for (int tt = 0; tt < NT; tt++) {
        int bid = (b * NT + tt) * NH + h;
        g_S[bid * HD + p] = c;
        c = g_Etot[bid] * c + g_carry[bid * HD + p];
    }
}

// ---------------- pass C: e/w + conv + scan + fixup + gate -> fp16 yh ----------------
__global__ void __launch_bounds__(64) k_scanC(const float* __restrict__ conv_w,
                                              const float* __restrict__ conv_b,
                                              const float* __restrict__ reward,
                                              const float* __restrict__ dt_bias,
                                              const float* __restrict__ A_log)
{
    const int bid = blockIdx.x;
    const int h = bid % NH;
    const int tt = (bid / NH) % NT;
    const int b = bid / (NH * NT);
    const int p = threadIdx.x;
    const int row0 = b * LL + tt * CHUNKT;
    const int c = h * HD + p;

    __shared__ float se[CHUNKT], sw[CHUNKT], sp[CHUNKT];
    {
        const int row = row0 + p;
        float raw = g_dt[(size_t)row * 32 + h] + dt_bias[h];
        float dtv = (raw > 20.f) ? raw : log1pf(__expf(raw));
        float a = -__expf(A_log[h]);
        se[p] = __expf(a * dtv);
        sw[p] = (reward[row] * g_scal[0] + g_scal[1]) * dtv;
    }
    __syncthreads();
    if (p == 0) {
        float r = 1.f;
        for (int i = 0; i < CHUNKT; i++) { r *= se[i]; sp[i] = r; }
    }
    __syncthreads();

    const float w0 = conv_w[c * 4 + 0], w1 = conv_w[c * 4 + 1];
    const float w2 = conv_w[c * 4 + 2], w3 = conv_w[c * 4 + 3];
    const float cb = conv_b[c];
    const float Sv = g_S[bid * HD + p];

    float x0 = 0.f, x1 = 0.f, x2 = 0.f;
    if (tt > 0) {
        x0 = __half2float(g_xh[(size_t)(row0 - 3) * DINNER + c]);
        x1 = __half2float(g_xh[(size_t)(row0 - 2) * DINNER + c]);
        x2 = __half2float(g_xh[(size_t)(row0 - 1) * DINNER + c]);
    }
    float r = 0.f;
    for (int i = 0; i < CHUNKT; i++) {
        const size_t rowi = (size_t)(row0 + i);
        float xn = __half2float(g_xh[rowi * DINNER + c]);
        float a = cb + x0 * w0 + x1 * w1 + x2 * w2 + xn * w3;
        r = se[i] * r + sw[i] * fsig(a);
        x0 = x1; x1 = x2; x2 = xn;
        float y = r + Sv * sp[i];
        float z = __half2float(g_zh[rowi * DINNER + c]);
        g_yh[rowi * DINNER + c] = __float2half_rn(y * fsig(z));
    }
}

// ---------------- launch ----------------
extern "C" void kernel_launch(void* const* d_in, const int* in_sizes, int n_in,
                              void* d_out, int out_size)
{
    const float* u       = (const float*)d_in[0];
    const float* reward  = (const float*)d_in[1];
    const float* in_w    = (const float*)d_in[2];
    const float* in_b    = (const float*)d_in[3];
    const float* conv_w  = (const float*)d_in[4];
    const float* conv_b  = (const float*)d_in[5];
    const float* bw      = (const float*)d_in[6];
    const float* bb      = (const float*)d_in[7];
    const float* dt_bias = (const float*)d_in[8];
    const float* A_log   = (const float*)d_in[9];
    const float* out_w   = (const float*)d_in[10];
    float* out = (float*)d_out;

    cudaFuncSetAttribute(k_mm, cudaFuncAttributeMaxDynamicSharedMemorySize, SMEM_DYN);

    float *dtp;
    __half *zhp, *xhp, *uh, *w1h, *yh, *w2h;
    cudaGetSymbolAddress((void**)&zhp, g_zh);
    cudaGetSymbolAddress((void**)&xhp, g_xh);
    cudaGetSymbolAddress((void**)&dtp, g_dt);
    cudaGetSymbolAddress((void**)&uh, g_uh);
    cudaGetSymbolAddress((void**)&w1h, g_w1h);
    cudaGetSymbolAddress((void**)&yh, g_yh);
    cudaGetSymbolAddress((void**)&w2h, g_w2h);

    // fused conversions (u, in_w, out_w)
    {
        size_t n = N_U + N_W1 + N_W2;
        k_convert<<<(unsigned)((n + 255) / 256), 256>>>(u, in_w, out_w);
    }

    // GEMM1: routed outputs z(fp16)/x(fp16)/dt(fp32)  (M=16384, K=1024)
    {
        dim3 grid(33, NROWS / BM);
        k_mm<<<grid, 128, SMEM_DYN>>>(uh, w1h, in_b, zhp, xhp, dtp, nullptr,
                                      NROWS, DIP, DMODEL, 1);
    }

    k_reduce_bwbb<<<1, 128>>>(bw, bb);
    k_scanA<<<BB * NT * NH, 64>>>(conv_w, conv_b, reward, dt_bias, A_log);
    {
        int n = BB * NH * HD;
        k_scanB<<<(n + 255) / 256, 256>>>();
    }
    k_scanC<<<BB * NT * NH, 64>>>(conv_w, conv_b, reward, dt_bias, A_log);

    // GEMM2: out[16384, 1024] = y_gated @ out_w^T  (K=2048)
    {
        dim3 grid(DMODEL / BN, NROWS / BM);
        k_mm<<<grid, 128, SMEM_DYN>>>(yh, w2h, nullptr, nullptr, nullptr, nullptr, out,
                                      NROWS, DMODEL, DINNER, 0);
    }
}